// round 2
// baseline (speedup 1.0000x reference)
#include <cuda_runtime.h>
#include <math.h>

#define Bb 2
#define LL 2048
#define DD 2048
#define HH 16
#define DHd 128
#define MM (Bb*LL)   // 4096

// Scratch (allocation-free): Q, K, V (post-proj, post-RoPE) and attention output.
__device__ float g_q[MM * DD];
__device__ float g_k[MM * DD];
__device__ float g_v[MM * DD];
__device__ float g_o[MM * DD];

// ---------------------------------------------------------------------------
// GEMM: C[M,N] = A[M,K] * W[N,K]^T   (M=MM, N=K=DD)
// mode 0: plain store. mode 1: fused RoPE epilogue (for Q and K projections).
// BM=BN=128, BK=8, 256 threads, 8x8 microtile per thread.
// ---------------------------------------------------------------------------
__global__ void __launch_bounds__(256) gemm_nt_kernel(
    const float* __restrict__ A, const float* __restrict__ W,
    float* __restrict__ C, const float* __restrict__ cosb,
    const float* __restrict__ sinb, int mode)
{
    __shared__ float As[8][128];
    __shared__ float Bs[8][128];

    const int tid = threadIdx.x;
    const int tx = tid & 15;        // 0..15 (n direction)
    const int ty = tid >> 4;        // 0..15 (m direction)
    const int m0 = blockIdx.y * 128;
    const int n0 = blockIdx.x * 128;

    // global load mapping: one float4 per thread per tile per operand
    const int lr = tid >> 1;          // row within tile (0..127)
    const int ls = (tid & 1) * 4;     // k-segment (0 or 4)
    const float* Ap = A + (size_t)(m0 + lr) * DD + ls;
    const float* Wp = W + (size_t)(n0 + lr) * DD + ls;

    float acc[8][8];
#pragma unroll
    for (int i = 0; i < 8; i++)
#pragma unroll
        for (int j = 0; j < 8; j++) acc[i][j] = 0.f;

    for (int k0 = 0; k0 < DD; k0 += 8) {
        float4 av = *(const float4*)(Ap + k0);
        float4 wv = *(const float4*)(Wp + k0);
        __syncthreads();
        As[ls + 0][lr] = av.x; As[ls + 1][lr] = av.y;
        As[ls + 2][lr] = av.z; As[ls + 3][lr] = av.w;
        Bs[ls + 0][lr] = wv.x; Bs[ls + 1][lr] = wv.y;
        Bs[ls + 2][lr] = wv.z; Bs[ls + 3][lr] = wv.w;
        __syncthreads();

#pragma unroll
        for (int kk = 0; kk < 8; kk++) {
            float4 a0 = *(const float4*)&As[kk][ty * 4];
            float4 a1 = *(const float4*)&As[kk][64 + ty * 4];
            float4 b0 = *(const float4*)&Bs[kk][tx * 4];
            float4 b1 = *(const float4*)&Bs[kk][64 + tx * 4];
            float a[8] = {a0.x, a0.y, a0.z, a0.w, a1.x, a1.y, a1.z, a1.w};
            float b[8] = {b0.x, b0.y, b0.z, b0.w, b1.x, b1.y, b1.z, b1.w};
#pragma unroll
            for (int i = 0; i < 8; i++)
#pragma unroll
                for (int j = 0; j < 8; j++)
                    acc[i][j] = fmaf(a[i], b[j], acc[i][j]);
        }
    }

    // epilogue
#pragma unroll
    for (int i = 0; i < 8; i++) {
        const int rm = m0 + ((i < 4) ? (ty * 4 + i) : (64 + ty * 4 + (i - 4)));
        const int l = rm & (LL - 1);
        float* Crow = C + (size_t)rm * DD;
#pragma unroll
        for (int jg = 0; jg < 2; jg++) {
            const int cn = n0 + (jg ? (64 + tx * 4) : (tx * 4));
            if (mode == 0) {
#pragma unroll
                for (int jj = 0; jj < 4; jj++) Crow[cn + jj] = acc[i][jg * 4 + jj];
            } else {
                // RoPE: columns come in adjacent (even, odd) pairs
#pragma unroll
                for (int p = 0; p < 2; p++) {
                    const int e  = cn + 2 * p;
                    const int ip = (e & (DHd - 1)) >> 1;
                    const float c = cosb[l * (DHd / 2) + ip];
                    const float s = sinb[l * (DHd / 2) + ip];
                    const float a0 = acc[i][jg * 4 + 2 * p];
                    const float a1 = acc[i][jg * 4 + 2 * p + 1];
                    Crow[e]     = a0 * c - a1 * s;
                    Crow[e + 1] = a0 * s + a1 * c;
                }
            }
        }
    }
}

// ---------------------------------------------------------------------------
// Flash attention (causal). Grid: (L/64 q-tiles, B*H). 256 threads.
// Per CTA: 64 q rows; stream 64-row K/V tiles (only t <= qt, causal skip).
// smem: qs/ks/vs [64][129] + ps [64][65]  ~113 KB.
// ---------------------------------------------------------------------------
#define QSS 129
#define PSS 65
#define ATTN_SMEM_FLOATS (3 * 64 * QSS + 64 * PSS)

__global__ void __launch_bounds__(256) attn_kernel(
    const float* __restrict__ q, const float* __restrict__ k,
    const float* __restrict__ v, float* __restrict__ o)
{
    extern __shared__ float sm[];
    float* qs = sm;
    float* ks = sm + 64 * QSS;
    float* vs = sm + 2 * 64 * QSS;
    float* ps = sm + 3 * 64 * QSS;

    const int tid = threadIdx.x;
    const int tx = tid & 15;   // score cols / O cols
    const int ty = tid >> 4;   // rows
    const int qt = blockIdx.x;
    const int bh = blockIdx.y;
    const int b = bh >> 4, h = bh & 15;
    const int q0 = qt * 64;
    const float scale = 0.08838834764831845f; // 1/sqrt(128)

    // load Q tile (pre-scaled)
    for (int i = tid; i < 64 * 32; i += 256) {
        const int r = i >> 5, c4 = (i & 31) * 4;
        float4 val = *(const float4*)(q + (size_t)(b * LL + q0 + r) * DD + h * DHd + c4);
        float* d = qs + r * QSS + c4;
        d[0] = val.x * scale; d[1] = val.y * scale;
        d[2] = val.z * scale; d[3] = val.w * scale;
    }

    float m_[4], l_[4], oacc[4][8];
#pragma unroll
    for (int i = 0; i < 4; i++) {
        m_[i] = -INFINITY; l_[i] = 0.f;
#pragma unroll
        for (int j = 0; j < 8; j++) oacc[i][j] = 0.f;
    }

    for (int t = 0; t <= qt; t++) {
        __syncthreads();   // protect ks/vs/ps reuse from previous iter (and q load)
        const int k0 = t * 64;
        for (int i = tid; i < 64 * 32; i += 256) {
            const int r = i >> 5, c4 = (i & 31) * 4;
            const size_t g = (size_t)(b * LL + k0 + r) * DD + h * DHd + c4;
            float4 kv = *(const float4*)(k + g);
            float4 vv = *(const float4*)(v + g);
            float* dk = ks + r * QSS + c4;
            dk[0] = kv.x; dk[1] = kv.y; dk[2] = kv.z; dk[3] = kv.w;
            float* dv = vs + r * QSS + c4;
            dv[0] = vv.x; dv[1] = vv.y; dv[2] = vv.z; dv[3] = vv.w;
        }
        __syncthreads();

        // S = Q * K^T (4x4 per thread)
        float sv[4][4];
#pragma unroll
        for (int i = 0; i < 4; i++)
#pragma unroll
            for (int j = 0; j < 4; j++) sv[i][j] = 0.f;

        for (int kk = 0; kk < DHd; kk++) {
            float a[4], bb[4];
#pragma unroll
            for (int i = 0; i < 4; i++) a[i] = qs[(ty * 4 + i) * QSS + kk];
#pragma unroll
            for (int j = 0; j < 4; j++) bb[j] = ks[(tx * 4 + j) * QSS + kk];
#pragma unroll
            for (int i = 0; i < 4; i++)
#pragma unroll
                for (int j = 0; j < 4; j++)
                    sv[i][j] = fmaf(a[i], bb[j], sv[i][j]);
        }

        // causal mask (only the diagonal tile needs it)
        if (t == qt) {
#pragma unroll
            for (int i = 0; i < 4; i++)
#pragma unroll
                for (int j = 0; j < 4; j++)
                    if (k0 + tx * 4 + j > q0 + ty * 4 + i) sv[i][j] = -1e30f;
        }

        // online softmax per row (row shared by the 16 tx-lanes of this ty)
#pragma unroll
        for (int i = 0; i < 4; i++) {
            float tm = sv[i][0];
#pragma unroll
            for (int j = 1; j < 4; j++) tm = fmaxf(tm, sv[i][j]);
#pragma unroll
            for (int d = 1; d < 16; d <<= 1)
                tm = fmaxf(tm, __shfl_xor_sync(0xffffffffu, tm, d));
            const float nm  = fmaxf(m_[i], tm);
            const float fac = __expf(m_[i] - nm);
            m_[i] = nm;
            float rs = 0.f;
#pragma unroll
            for (int j = 0; j < 4; j++) {
                sv[i][j] = __expf(sv[i][j] - nm);
                rs += sv[i][j];
            }
#pragma unroll
            for (int d = 1; d < 16; d <<= 1)
                rs += __shfl_xor_sync(0xffffffffu, rs, d);
            l_[i] = l_[i] * fac + rs;
#pragma unroll
            for (int j = 0; j < 8; j++) oacc[i][j] *= fac;
        }

        // stage P through smem
#pragma unroll
        for (int i = 0; i < 4; i++)
#pragma unroll
            for (int j = 0; j < 4; j++)
                ps[(ty * 4 + i) * PSS + tx * 4 + j] = sv[i][j];
        __syncthreads();

        // O += P * V  (rows ty*4.., cols tx*8..)
        for (int c = 0; c < 64; c++) {
            float pv[4];
#pragma unroll
            for (int i = 0; i < 4; i++) pv[i] = ps[(ty * 4 + i) * PSS + c];
#pragma unroll
            for (int j = 0; j < 8; j++) {
                const float vvj = vs[c * QSS + tx * 8 + j];
#pragma unroll
                for (int i = 0; i < 4; i++)
                    oacc[i][j] = fmaf(pv[i], vvj, oacc[i][j]);
            }
        }
    }

    // normalize + store
#pragma unroll
    for (int i = 0; i < 4; i++) {
        const float inv = 1.f / l_[i];
        const size_t row = (size_t)(b * LL + q0 + ty * 4 + i) * DD + h * DHd + tx * 8;
#pragma unroll
        for (int j = 0; j < 8; j++) o[row + j] = oacc[i][j] * inv;
    }
}

// ---------------------------------------------------------------------------
extern "C" void kernel_launch(void* const* d_in, const int* in_sizes, int n_in,
                              void* d_out, int out_size)
{
    const float* x    = (const float*)d_in[0];
    // d_in[1] = mask (ignored; causal structure known)
    const float* cosb = (const float*)d_in[2];
    const float* sinb = (const float*)d_in[3];
    const float* wq   = (const float*)d_in[4];
    const float* wk   = (const float*)d_in[5];
    const float* wv   = (const float*)d_in[6];
    const float* wo   = (const float*)d_in[7];
    float* out = (float*)d_out;

    float *qp, *kp, *vp, *op;
    cudaGetSymbolAddress((void**)&qp, g_q);
    cudaGetSymbolAddress((void**)&kp, g_k);
    cudaGetSymbolAddress((void**)&vp, g_v);
    cudaGetSymbolAddress((void**)&op, g_o);

    dim3 gb(DD / 128, MM / 128);   // (16, 32)
    gemm_nt_kernel<<<gb, 256>>>(x, wq, qp, cosb, sinb, 1);
    gemm_nt_kernel<<<gb, 256>>>(x, wk, kp, cosb, sinb, 1);
    gemm_nt_kernel<<<gb, 256>>>(x, wv, vp, cosb, sinb, 0);

    const size_t smem = ATTN_SMEM_FLOATS * sizeof(float);
    cudaFuncSetAttribute(attn_kernel,
                         cudaFuncAttributeMaxDynamicSharedMemorySize, (int)smem);
    attn_kernel<<<dim3(LL / 64, Bb * HH), 256, smem>>>(qp, kp, vp, op);

    gemm_nt_kernel<<<gb, 256>>>(op, wo, out, cosb, sinb, 0);
}

// round 4
// speedup vs baseline: 1.4998x; 1.4998x over previous
#include <cuda_runtime.h>
#include <cuda_bf16.h>
#include <math.h>
#include <stdint.h>

#define Bb 2
#define LL 2048
#define DD 2048
#define HH 16
#define DHd 128
#define MM (Bb*LL)   // 4096

// Scratch (allocation-free)
__device__ float g_q[MM * DD];
__device__ float g_k[MM * DD];
__device__ float g_v[MM * DD];
__device__ float g_o[MM * DD];
__device__ __nv_bfloat16 g_ah[MM * DD];
__device__ __nv_bfloat16 g_al[MM * DD];
__device__ __nv_bfloat16 g_wh[4 * DD * DD];
__device__ __nv_bfloat16 g_wl[4 * DD * DD];

// ---------------------------------------------------------------------------
// PTX helpers (non-'a' target safe: mma.sync / ldmatrix / cp.async only)
// ---------------------------------------------------------------------------
__device__ __forceinline__ uint32_t s2u(const void* p) {
    uint32_t a;
    asm("{ .reg .u64 t; cvta.to.shared.u64 t, %1; cvt.u32.u64 %0, t; }"
        : "=r"(a) : "l"(p));
    return a;
}
__device__ __forceinline__ void cp16(uint32_t so, const void* g) {
    asm volatile("cp.async.cg.shared.global [%0], [%1], 16;" :: "r"(so), "l"(g));
}
#define CP_COMMIT() asm volatile("cp.async.commit_group;" ::: "memory")
#define CP_WAIT(n)  asm volatile("cp.async.wait_group %0;" :: "n"(n) : "memory")

__device__ __forceinline__ void ldsm4(uint32_t* d, uint32_t a) {
    asm volatile("ldmatrix.sync.aligned.m8n8.x4.shared.b16 {%0,%1,%2,%3}, [%4];"
                 : "=r"(d[0]), "=r"(d[1]), "=r"(d[2]), "=r"(d[3]) : "r"(a));
}
__device__ __forceinline__ void mma16816(float* c, const uint32_t* a,
                                         uint32_t b0, uint32_t b1) {
    asm volatile(
        "mma.sync.aligned.m16n8k16.row.col.f32.bf16.bf16.f32 "
        "{%0,%1,%2,%3}, {%4,%5,%6,%7}, {%8,%9}, {%0,%1,%2,%3};"
        : "+f"(c[0]), "+f"(c[1]), "+f"(c[2]), "+f"(c[3])
        : "r"(a[0]), "r"(a[1]), "r"(a[2]), "r"(a[3]), "r"(b0), "r"(b1));
}

// ---------------------------------------------------------------------------
// Split fp32 -> bf16 hi/lo
// ---------------------------------------------------------------------------
__global__ void __launch_bounds__(256) split_bf16(
    const float* __restrict__ s, __nv_bfloat16* __restrict__ h,
    __nv_bfloat16* __restrict__ l, int n4)
{
    int i = blockIdx.x * 256 + threadIdx.x;
    if (i >= n4) return;
    float4 f = ((const float4*)s)[i];
    float fv[4] = {f.x, f.y, f.z, f.w};
    __nv_bfloat16 hh[4], ll[4];
#pragma unroll
    for (int j = 0; j < 4; j++) {
        hh[j] = __float2bfloat16(fv[j]);
        ll[j] = __float2bfloat16(fv[j] - __bfloat162float(hh[j]));
    }
    ((__nv_bfloat162*)h)[2*i]   = __halves2bfloat162(hh[0], hh[1]);
    ((__nv_bfloat162*)h)[2*i+1] = __halves2bfloat162(hh[2], hh[3]);
    ((__nv_bfloat162*)l)[2*i]   = __halves2bfloat162(ll[0], ll[1]);
    ((__nv_bfloat162*)l)[2*i+1] = __halves2bfloat162(ll[2], ll[3]);
}

// ---------------------------------------------------------------------------
// mma.sync GEMM: C[M,N] = A * W^T, bf16 hi/lo 3-product split, fp32 accum.
// BM=128 BN=128 BK=32, 256 thr (8 warps: 4m x 2n, warp tile 32x64).
// smem rows: 32 bf16 = 64B padded to 80B (conflict-free ldmatrix).
// mode 1: fused RoPE on C fragments.
// ---------------------------------------------------------------------------
#define ROWB 80
#define TILEB (128 * ROWB)          // 10240 per operand
#define STGB  (4 * TILEB)           // 40960 per stage
#define GSMEM (2 * STGB)            // 81920

__device__ __forceinline__ void load_stage(
    uint32_t sb, int stage, int tid, int m0, int n0, int kt,
    const __nv_bfloat16* __restrict__ Ah, const __nv_bfloat16* __restrict__ Al,
    const __nv_bfloat16* __restrict__ Wh, const __nv_bfloat16* __restrict__ Wl)
{
    const uint32_t base = sb + stage * STGB;
    const int k0 = kt * 32;
#pragma unroll
    for (int j = 0; j < 2; j++) {
        const int idx = tid + j * 256;
        const int r = idx >> 2, c16 = idx & 3;
        const uint32_t so = r * ROWB + c16 * 16;
        const size_t ga = (size_t)(m0 + r) * DD + k0 + c16 * 8;
        const size_t gw = (size_t)(n0 + r) * DD + k0 + c16 * 8;
        cp16(base + so,             Ah + ga);
        cp16(base + TILEB + so,     Al + ga);
        cp16(base + 2 * TILEB + so, Wh + gw);
        cp16(base + 3 * TILEB + so, Wl + gw);
    }
}

__global__ void __launch_bounds__(256) gemm_mma(
    const __nv_bfloat16* __restrict__ Ah, const __nv_bfloat16* __restrict__ Al,
    const __nv_bfloat16* __restrict__ Wh, const __nv_bfloat16* __restrict__ Wl,
    float* __restrict__ C, const float* __restrict__ cosb,
    const float* __restrict__ sinb, int mode)
{
    extern __shared__ char sm[];
    const uint32_t sb = s2u(sm);
    const int tid = threadIdx.x, wid = tid >> 5, lid = tid & 31;
    const int m0 = blockIdx.y * 128, n0 = blockIdx.x * 128;
    const int m0w = (wid & 3) * 32;      // warp m offset
    const int n0w = (wid >> 2) * 64;     // warp n offset

    float acc[2][8][4];
#pragma unroll
    for (int a = 0; a < 2; a++)
#pragma unroll
        for (int b = 0; b < 8; b++)
#pragma unroll
            for (int c = 0; c < 4; c++) acc[a][b][c] = 0.f;

    load_stage(sb, 0, tid, m0, n0, 0, Ah, Al, Wh, Wl);
    CP_COMMIT();

    const int lr = lid & 15, lh = lid >> 4;

    for (int kt = 0; kt < 64; kt++) {
        const int s = kt & 1;
        if (kt + 1 < 64) {
            load_stage(sb, s ^ 1, tid, m0, n0, kt + 1, Ah, Al, Wh, Wl);
            CP_COMMIT();
            CP_WAIT(1);
        } else {
            CP_WAIT(0);
        }
        __syncthreads();

        const uint32_t bA  = sb + s * STGB;
        const uint32_t bAl = bA + TILEB;
        const uint32_t bWh = bA + 2 * TILEB;
        const uint32_t bWl = bA + 3 * TILEB;

#pragma unroll
        for (int kk = 0; kk < 2; kk++) {
            const int c16 = kk * 2 + lh;
            uint32_t ah[2][4], al[2][4];
#pragma unroll
            for (int mt = 0; mt < 2; mt++) {
                const int r = m0w + mt * 16 + lr;
                const uint32_t off = r * ROWB + c16 * 16;
                ldsm4(ah[mt], bA + off);
                ldsm4(al[mt], bAl + off);
            }
#pragma unroll
            for (int g = 0; g < 4; g++) {
                const int rn = n0w + g * 16 + lr;
                const uint32_t offb = rn * ROWB + c16 * 16;
                uint32_t bh[4], bl[4];
                ldsm4(bh, bWh + offb);
                ldsm4(bl, bWl + offb);
#pragma unroll
                for (int mt = 0; mt < 2; mt++) {
#pragma unroll
                    for (int nt = 0; nt < 2; nt++) {
                        float* cc = acc[mt][g * 2 + nt];
                        mma16816(cc, ah[mt], bh[nt], bh[nt + 2]);
                        mma16816(cc, ah[mt], bl[nt], bl[nt + 2]);
                        mma16816(cc, al[mt], bh[nt], bh[nt + 2]);
                    }
                }
            }
        }
        __syncthreads();
    }

    // Epilogue: fragments -> global, RoPE fused (col pairs are adjacent per lane)
    const int gid = lid >> 2, tig = lid & 3;
#pragma unroll
    for (int mt = 0; mt < 2; mt++) {
#pragma unroll
        for (int nt8 = 0; nt8 < 8; nt8++) {
            const float* cc = acc[mt][nt8];
            const int gn = n0 + n0w + nt8 * 8 + tig * 2;
#pragma unroll
            for (int hrow = 0; hrow < 2; hrow++) {
                const int m = m0 + m0w + mt * 16 + gid + hrow * 8;
                float v0 = cc[hrow * 2], v1 = cc[hrow * 2 + 1];
                if (mode) {
                    const int lrow = m & (LL - 1);
                    const int ip = (gn & (DHd - 1)) >> 1;
                    const float co = cosb[lrow * 64 + ip];
                    const float si = sinb[lrow * 64 + ip];
                    const float t0 = v0 * co - v1 * si;
                    const float t1 = v0 * si + v1 * co;
                    v0 = t0; v1 = t1;
                }
                *(float2*)(C + (size_t)m * DD + gn) = make_float2(v0, v1);
            }
        }
    }
}

// ---------------------------------------------------------------------------
// Flash attention (causal) — fp32, unchanged from R2.
// ---------------------------------------------------------------------------
#define QSS 129
#define PSS 65
#define ATTN_SMEM_FLOATS (3 * 64 * QSS + 64 * PSS)

__global__ void __launch_bounds__(256) attn_kernel(
    const float* __restrict__ q, const float* __restrict__ k,
    const float* __restrict__ v, float* __restrict__ o)
{
    extern __shared__ float smf[];
    float* qs = smf;
    float* ks = smf + 64 * QSS;
    float* vs = smf + 2 * 64 * QSS;
    float* ps = smf + 3 * 64 * QSS;

    const int tid = threadIdx.x;
    const int tx = tid & 15;
    const int ty = tid >> 4;
    const int qt = blockIdx.x;
    const int bh = blockIdx.y;
    const int b = bh >> 4, h = bh & 15;
    const int q0 = qt * 64;
    const float scale = 0.08838834764831845f;

    for (int i = tid; i < 64 * 32; i += 256) {
        const int r = i >> 5, c4 = (i & 31) * 4;
        float4 val = *(const float4*)(q + (size_t)(b * LL + q0 + r) * DD + h * DHd + c4);
        float* d = qs + r * QSS + c4;
        d[0] = val.x * scale; d[1] = val.y * scale;
        d[2] = val.z * scale; d[3] = val.w * scale;
    }

    float m_[4], l_[4], oacc[4][8];
#pragma unroll
    for (int i = 0; i < 4; i++) {
        m_[i] = -INFINITY; l_[i] = 0.f;
#pragma unroll
        for (int j = 0; j < 8; j++) oacc[i][j] = 0.f;
    }

    for (int t = 0; t <= qt; t++) {
        __syncthreads();
        const int k0 = t * 64;
        for (int i = tid; i < 64 * 32; i += 256) {
            const int r = i >> 5, c4 = (i & 31) * 4;
            const size_t g = (size_t)(b * LL + k0 + r) * DD + h * DHd + c4;
            float4 kv = *(const float4*)(k + g);
            float4 vv = *(const float4*)(v + g);
            float* dk = ks + r * QSS + c4;
            dk[0] = kv.x; dk[1] = kv.y; dk[2] = kv.z; dk[3] = kv.w;
            float* dv = vs + r * QSS + c4;
            dv[0] = vv.x; dv[1] = vv.y; dv[2] = vv.z; dv[3] = vv.w;
        }
        __syncthreads();

        float sv[4][4];
#pragma unroll
        for (int i = 0; i < 4; i++)
#pragma unroll
            for (int j = 0; j < 4; j++) sv[i][j] = 0.f;

        for (int kk = 0; kk < DHd; kk++) {
            float a[4], bb[4];
#pragma unroll
            for (int i = 0; i < 4; i++) a[i] = qs[(ty * 4 + i) * QSS + kk];
#pragma unroll
            for (int j = 0; j < 4; j++) bb[j] = ks[(tx * 4 + j) * QSS + kk];
#pragma unroll
            for (int i = 0; i < 4; i++)
#pragma unroll
                for (int j = 0; j < 4; j++)
                    sv[i][j] = fmaf(a[i], bb[j], sv[i][j]);
        }

        if (t == qt) {
#pragma unroll
            for (int i = 0; i < 4; i++)
#pragma unroll
                for (int j = 0; j < 4; j++)
                    if (k0 + tx * 4 + j > q0 + ty * 4 + i) sv[i][j] = -1e30f;
        }

#pragma unroll
        for (int i = 0; i < 4; i++) {
            float tm = sv[i][0];
#pragma unroll
            for (int j = 1; j < 4; j++) tm = fmaxf(tm, sv[i][j]);
#pragma unroll
            for (int d = 1; d < 16; d <<= 1)
                tm = fmaxf(tm, __shfl_xor_sync(0xffffffffu, tm, d));
            const float nm  = fmaxf(m_[i], tm);
            const float fac = __expf(m_[i] - nm);
            m_[i] = nm;
            float rs = 0.f;
#pragma unroll
            for (int j = 0; j < 4; j++) {
                sv[i][j] = __expf(sv[i][j] - nm);
                rs += sv[i][j];
            }
#pragma unroll
            for (int d = 1; d < 16; d <<= 1)
                rs += __shfl_xor_sync(0xffffffffu, rs, d);
            l_[i] = l_[i] * fac + rs;
#pragma unroll
            for (int j = 0; j < 8; j++) oacc[i][j] *= fac;
        }

#pragma unroll
        for (int i = 0; i < 4; i++)
#pragma unroll
            for (int j = 0; j < 4; j++)
                ps[(ty * 4 + i) * PSS + tx * 4 + j] = sv[i][j];
        __syncthreads();

        for (int c = 0; c < 64; c++) {
            float pv[4];
#pragma unroll
            for (int i = 0; i < 4; i++) pv[i] = ps[(ty * 4 + i) * PSS + c];
#pragma unroll
            for (int j = 0; j < 8; j++) {
                const float vvj = vs[c * QSS + tx * 8 + j];
#pragma unroll
                for (int i = 0; i < 4; i++)
                    oacc[i][j] = fmaf(pv[i], vvj, oacc[i][j]);
            }
        }
    }

#pragma unroll
    for (int i = 0; i < 4; i++) {
        const float inv = 1.f / l_[i];
        const size_t row = (size_t)(b * LL + q0 + ty * 4 + i) * DD + h * DHd + tx * 8;
#pragma unroll
        for (int j = 0; j < 8; j++) o[row + j] = oacc[i][j] * inv;
    }
}

// ---------------------------------------------------------------------------
extern "C" void kernel_launch(void* const* d_in, const int* in_sizes, int n_in,
                              void* d_out, int out_size)
{
    const float* x    = (const float*)d_in[0];
    const float* cosb = (const float*)d_in[2];
    const float* sinb = (const float*)d_in[3];
    const float* wq   = (const float*)d_in[4];
    const float* wk   = (const float*)d_in[5];
    const float* wv   = (const float*)d_in[6];
    const float* wo   = (const float*)d_in[7];
    float* out = (float*)d_out;

    float *qp, *kp, *vp, *op;
    __nv_bfloat16 *ah, *al, *wh, *wl;
    cudaGetSymbolAddress((void**)&qp, g_q);
    cudaGetSymbolAddress((void**)&kp, g_k);
    cudaGetSymbolAddress((void**)&vp, g_v);
    cudaGetSymbolAddress((void**)&op, g_o);
    cudaGetSymbolAddress((void**)&ah, g_ah);
    cudaGetSymbolAddress((void**)&al, g_al);
    cudaGetSymbolAddress((void**)&wh, g_wh);
    cudaGetSymbolAddress((void**)&wl, g_wl);

    const int n4x = MM * DD / 4;
    const int n4w = DD * DD / 4;
    const int SL = DD * DD;

    split_bf16<<<n4x / 256, 256>>>(x,  ah, al, n4x);
    split_bf16<<<n4w / 256, 256>>>(wq, wh + 0 * SL, wl + 0 * SL, n4w);
    split_bf16<<<n4w / 256, 256>>>(wk, wh + 1 * SL, wl + 1 * SL, n4w);
    split_bf16<<<n4w / 256, 256>>>(wv, wh + 2 * SL, wl + 2 * SL, n4w);
    split_bf16<<<n4w / 256, 256>>>(wo, wh + 3 * SL, wl + 3 * SL, n4w);

    cudaFuncSetAttribute(gemm_mma, cudaFuncAttributeMaxDynamicSharedMemorySize, GSMEM);
    dim3 gg(DD / 128, MM / 128);  // (16, 32)
    gemm_mma<<<gg, 256, GSMEM>>>(ah, al, wh + 0 * SL, wl + 0 * SL, qp, cosb, sinb, 1);
    gemm_mma<<<gg, 256, GSMEM>>>(ah, al, wh + 1 * SL, wl + 1 * SL, kp, cosb, sinb, 1);
    gemm_mma<<<gg, 256, GSMEM>>>(ah, al, wh + 2 * SL, wl + 2 * SL, vp, cosb, sinb, 0);

    const size_t asmem = ATTN_SMEM_FLOATS * sizeof(float);
    cudaFuncSetAttribute(attn_kernel, cudaFuncAttributeMaxDynamicSharedMemorySize, (int)asmem);
    attn_kernel<<<dim3(LL / 64, Bb * HH), 256, asmem>>>(qp, kp, vp, op);

    split_bf16<<<n4x / 256, 256>>>(op, ah, al, n4x);
    gemm_mma<<<gg, 256, GSMEM>>>(ah, al, wh + 3 * SL, wl + 3 * SL, out, cosb, sinb, 0);
}

// round 5
// speedup vs baseline: 2.7132x; 1.8091x over previous
#include <cuda_runtime.h>
#include <cuda_bf16.h>
#include <math.h>
#include <stdint.h>

#define Bb 2
#define LL 2048
#define DD 2048
#define HH 16
#define DHd 128
#define MM (Bb*LL)   // 4096

// Scratch (allocation-free), all bf16 hi/lo pairs
__device__ __nv_bfloat16 g_ah[MM * DD];
__device__ __nv_bfloat16 g_al[MM * DD];
__device__ __nv_bfloat16 g_wh[4 * DD * DD];
__device__ __nv_bfloat16 g_wl[4 * DD * DD];
__device__ __nv_bfloat16 g_qh[MM * DD];
__device__ __nv_bfloat16 g_ql[MM * DD];
__device__ __nv_bfloat16 g_kh[MM * DD];
__device__ __nv_bfloat16 g_kl[MM * DD];
__device__ __nv_bfloat16 g_vh[MM * DD];
__device__ __nv_bfloat16 g_vl[MM * DD];
__device__ __nv_bfloat16 g_oh[MM * DD];
__device__ __nv_bfloat16 g_ol[MM * DD];

// ---------------------------------------------------------------------------
// PTX helpers (non-'a' target: mma.sync / ldmatrix / cp.async)
// ---------------------------------------------------------------------------
__device__ __forceinline__ uint32_t s2u(const void* p) {
    uint32_t a;
    asm("{ .reg .u64 t; cvta.to.shared.u64 t, %1; cvt.u32.u64 %0, t; }"
        : "=r"(a) : "l"(p));
    return a;
}
__device__ __forceinline__ void cp16(uint32_t so, const void* g) {
    asm volatile("cp.async.cg.shared.global [%0], [%1], 16;" :: "r"(so), "l"(g));
}
#define CP_COMMIT() asm volatile("cp.async.commit_group;" ::: "memory")
#define CP_WAIT(n)  asm volatile("cp.async.wait_group %0;" :: "n"(n) : "memory")

__device__ __forceinline__ void ldsm4(uint32_t* d, uint32_t a) {
    asm volatile("ldmatrix.sync.aligned.m8n8.x4.shared.b16 {%0,%1,%2,%3}, [%4];"
                 : "=r"(d[0]), "=r"(d[1]), "=r"(d[2]), "=r"(d[3]) : "r"(a));
}
__device__ __forceinline__ void ldsm4t(uint32_t* d, uint32_t a) {
    asm volatile("ldmatrix.sync.aligned.m8n8.x4.trans.shared.b16 {%0,%1,%2,%3}, [%4];"
                 : "=r"(d[0]), "=r"(d[1]), "=r"(d[2]), "=r"(d[3]) : "r"(a));
}
__device__ __forceinline__ void mma16816(float* c, const uint32_t* a,
                                         uint32_t b0, uint32_t b1) {
    asm volatile(
        "mma.sync.aligned.m16n8k16.row.col.f32.bf16.bf16.f32 "
        "{%0,%1,%2,%3}, {%4,%5,%6,%7}, {%8,%9}, {%0,%1,%2,%3};"
        : "+f"(c[0]), "+f"(c[1]), "+f"(c[2]), "+f"(c[3])
        : "r"(a[0]), "r"(a[1]), "r"(a[2]), "r"(a[3]), "r"(b0), "r"(b1));
}
__device__ __forceinline__ void split2(float f0, float f1,
                                       __nv_bfloat162& h, __nv_bfloat162& l) {
    h = __floats2bfloat162_rn(f0, f1);
    float2 hf = __bfloat1622float2(h);
    l = __floats2bfloat162_rn(f0 - hf.x, f1 - hf.y);
}

// ---------------------------------------------------------------------------
// Split fp32 -> bf16 hi/lo (x and weights only)
// ---------------------------------------------------------------------------
__global__ void __launch_bounds__(256) split_bf16(
    const float* __restrict__ s, __nv_bfloat16* __restrict__ h,
    __nv_bfloat16* __restrict__ l, int n4)
{
    int i = blockIdx.x * 256 + threadIdx.x;
    if (i >= n4) return;
    float4 f = ((const float4*)s)[i];
    __nv_bfloat162 h0, h1, l0, l1;
    split2(f.x, f.y, h0, l0);
    split2(f.z, f.w, h1, l1);
    ((__nv_bfloat162*)h)[2*i]   = h0;
    ((__nv_bfloat162*)h)[2*i+1] = h1;
    ((__nv_bfloat162*)l)[2*i]   = l0;
    ((__nv_bfloat162*)l)[2*i+1] = l1;
}

// ---------------------------------------------------------------------------
// GEMM: C = A*W^T, bf16 hi/lo 3-product, fp32 accum.  BM=BN=128, BK=32.
// 3-stage cp.async pipeline, ONE __syncthreads per k-iter.
// mode: 0 fp32 store -> Cf;  1 RoPE+split -> Ch/Cl;  2 RoPE+scale+split;  3 split
// ---------------------------------------------------------------------------
#define ROWB 80
#define TILEB (128 * ROWB)
#define STGB  (4 * TILEB)           // 40960
#define GSMEM (3 * STGB)            // 122880

__device__ __forceinline__ void load_stage(
    uint32_t sb, int stage, int tid, int m0, int n0, int kt,
    const __nv_bfloat16* __restrict__ Ah, const __nv_bfloat16* __restrict__ Al,
    const __nv_bfloat16* __restrict__ Wh, const __nv_bfloat16* __restrict__ Wl)
{
    const uint32_t base = sb + stage * STGB;
    const int k0 = kt * 32;
#pragma unroll
    for (int j = 0; j < 2; j++) {
        const int idx = tid + j * 256;
        const int r = idx >> 2, c16 = idx & 3;
        const uint32_t so = r * ROWB + c16 * 16;
        const size_t ga = (size_t)(m0 + r) * DD + k0 + c16 * 8;
        const size_t gw = (size_t)(n0 + r) * DD + k0 + c16 * 8;
        cp16(base + so,             Ah + ga);
        cp16(base + TILEB + so,     Al + ga);
        cp16(base + 2 * TILEB + so, Wh + gw);
        cp16(base + 3 * TILEB + so, Wl + gw);
    }
}

__global__ void __launch_bounds__(256) gemm_mma(
    const __nv_bfloat16* __restrict__ Ah, const __nv_bfloat16* __restrict__ Al,
    const __nv_bfloat16* __restrict__ Wh, const __nv_bfloat16* __restrict__ Wl,
    float* __restrict__ Cf, __nv_bfloat16* __restrict__ Ch,
    __nv_bfloat16* __restrict__ Cl, const float* __restrict__ cosb,
    const float* __restrict__ sinb, int mode)
{
    extern __shared__ char sm[];
    const uint32_t sb = s2u(sm);
    const int tid = threadIdx.x, wid = tid >> 5, lid = tid & 31;
    const int m0 = blockIdx.y * 128, n0 = blockIdx.x * 128;
    const int m0w = (wid & 3) * 32;
    const int n0w = (wid >> 2) * 64;

    float acc[2][8][4];
#pragma unroll
    for (int a = 0; a < 2; a++)
#pragma unroll
        for (int b = 0; b < 8; b++)
#pragma unroll
            for (int c = 0; c < 4; c++) acc[a][b][c] = 0.f;

    load_stage(sb, 0, tid, m0, n0, 0, Ah, Al, Wh, Wl);
    CP_COMMIT();
    load_stage(sb, 1, tid, m0, n0, 1, Ah, Al, Wh, Wl);
    CP_COMMIT();

    const int lr = lid & 15, lh = lid >> 4;

    for (int kt = 0; kt < 64; kt++) {
        if (kt + 1 < 64) { CP_WAIT(1); } else { CP_WAIT(0); }
        __syncthreads();
        if (kt + 2 < 64) {
            load_stage(sb, (kt + 2) % 3, tid, m0, n0, kt + 2, Ah, Al, Wh, Wl);
            CP_COMMIT();
        }
        const uint32_t bA  = sb + (kt % 3) * STGB;
        const uint32_t bAl = bA + TILEB;
        const uint32_t bWh = bA + 2 * TILEB;
        const uint32_t bWl = bA + 3 * TILEB;

#pragma unroll
        for (int kk = 0; kk < 2; kk++) {
            const int c16 = kk * 2 + lh;
            uint32_t ah[2][4], al[2][4];
#pragma unroll
            for (int mt = 0; mt < 2; mt++) {
                const int r = m0w + mt * 16 + lr;
                const uint32_t off = r * ROWB + c16 * 16;
                ldsm4(ah[mt], bA + off);
                ldsm4(al[mt], bAl + off);
            }
#pragma unroll
            for (int g = 0; g < 4; g++) {
                const int rn = n0w + g * 16 + lr;
                const uint32_t offb = rn * ROWB + c16 * 16;
                uint32_t bh[4], bl[4];
                ldsm4(bh, bWh + offb);
                ldsm4(bl, bWl + offb);
#pragma unroll
                for (int mt = 0; mt < 2; mt++) {
#pragma unroll
                    for (int nt = 0; nt < 2; nt++) {
                        float* cc = acc[mt][g * 2 + nt];
                        mma16816(cc, ah[mt], bh[nt], bh[nt + 2]);
                        mma16816(cc, ah[mt], bl[nt], bl[nt + 2]);
                        mma16816(cc, al[mt], bh[nt], bh[nt + 2]);
                    }
                }
            }
        }
    }

    // Epilogue
    const int gid = lid >> 2, tig = lid & 3;
#pragma unroll
    for (int mt = 0; mt < 2; mt++) {
#pragma unroll
        for (int nt8 = 0; nt8 < 8; nt8++) {
            const float* cc = acc[mt][nt8];
            const int gn = n0 + n0w + nt8 * 8 + tig * 2;
#pragma unroll
            for (int hrow = 0; hrow < 2; hrow++) {
                const int m = m0 + m0w + mt * 16 + gid + hrow * 8;
                float v0 = cc[hrow * 2], v1 = cc[hrow * 2 + 1];
                if (mode == 1 || mode == 2) {
                    const int lrow = m & (LL - 1);
                    const int ip = (gn & (DHd - 1)) >> 1;
                    const float co = cosb[lrow * 64 + ip];
                    const float si = sinb[lrow * 64 + ip];
                    const float t0 = v0 * co - v1 * si;
                    const float t1 = v0 * si + v1 * co;
                    v0 = t0; v1 = t1;
                    if (mode == 2) { v0 *= 0.08838834764831845f; v1 *= 0.08838834764831845f; }
                }
                const size_t gidx = (size_t)m * DD + gn;
                if (mode == 0) {
                    *(float2*)(Cf + gidx) = make_float2(v0, v1);
                } else {
                    __nv_bfloat162 hb, lb;
                    split2(v0, v1, hb, lb);
                    *(__nv_bfloat162*)(Ch + gidx) = hb;
                    *(__nv_bfloat162*)(Cl + gidx) = lb;
                }
            }
        }
    }
}

// ---------------------------------------------------------------------------
// Flash attention, mma.sync, hi/lo 3-product for S and PV.
// CTA: 128 q rows, 8 warps x 16 rows. 64-key tiles, double-buffered cp.async.
// smem: Qh/Ql (128x272B each) + 2 stages of {Kh,Kl,Vh,Vl} (64x272B each).
// ---------------------------------------------------------------------------
#define APITCH 272
#define QBYTES (128 * APITCH)        // 34816
#define KVSTG  (4 * 64 * APITCH)     // 69632
#define ASMEM  (2 * QBYTES + 2 * KVSTG)  // 208896

__device__ __forceinline__ void load_kv(
    uint32_t sb, int stage, int tid, int b, int k0, int h,
    const __nv_bfloat16* __restrict__ Kh, const __nv_bfloat16* __restrict__ Kl,
    const __nv_bfloat16* __restrict__ Vh, const __nv_bfloat16* __restrict__ Vl)
{
    const uint32_t base = sb + 2 * QBYTES + stage * KVSTG;
#pragma unroll
    for (int j = 0; j < 4; j++) {
        const int i = tid + j * 256;
        const int r = i >> 4, c = i & 15;
        const uint32_t off = r * APITCH + c * 16;
        const size_t g = (size_t)(b * LL + k0 + r) * DD + h * DHd + c * 8;
        cp16(base + off,             Kh + g);
        cp16(base + 17408 + off,     Kl + g);
        cp16(base + 34816 + off,     Vh + g);
        cp16(base + 52224 + off,     Vl + g);
    }
}

__global__ void __launch_bounds__(256, 1) attn_mma(
    const __nv_bfloat16* __restrict__ Qh, const __nv_bfloat16* __restrict__ Ql,
    const __nv_bfloat16* __restrict__ Kh, const __nv_bfloat16* __restrict__ Kl,
    const __nv_bfloat16* __restrict__ Vh, const __nv_bfloat16* __restrict__ Vl,
    __nv_bfloat16* __restrict__ Oh, __nv_bfloat16* __restrict__ Ol)
{
    extern __shared__ char sm[];
    const uint32_t sb = s2u(sm);
    const int tid = threadIdx.x, wid = tid >> 5, lid = tid & 31;
    const int lr = lid & 15, lh = lid >> 4;
    const int gid = lid >> 2, tig = lid & 3;
    const int qt = blockIdx.x, bh = blockIdx.y;
    const int b = bh >> 4, h = bh & 15;
    const int q0 = qt * 128;

    // Q tiles (hi/lo) via cp.async  (group 0)
#pragma unroll
    for (int j = 0; j < 8; j++) {
        const int i = tid + j * 256;
        const int r = i >> 4, c = i & 15;
        const size_t g = (size_t)(b * LL + q0 + r) * DD + h * DHd + c * 8;
        const uint32_t off = r * APITCH + c * 16;
        cp16(sb + off, Qh + g);
        cp16(sb + QBYTES + off, Ql + g);
    }
    CP_COMMIT();
    load_kv(sb, 0, tid, b, 0, h, Kh, Kl, Vh, Vl);   // group 1
    CP_COMMIT();

    CP_WAIT(1);          // Q ready
    __syncthreads();

    // Build Q fragments (held in registers for the whole kernel)
    uint32_t qfh[8][4], qfl[8][4];
    const int wrow = wid * 16;
#pragma unroll
    for (int kc = 0; kc < 8; kc++) {
        const uint32_t off = (wrow + lr) * APITCH + (kc * 2 + lh) * 16;
        ldsm4(qfh[kc], sb + off);
        ldsm4(qfl[kc], sb + QBYTES + off);
    }

    float oacc[16][4];
#pragma unroll
    for (int i = 0; i < 16; i++)
#pragma unroll
        for (int j = 0; j < 4; j++) oacc[i][j] = 0.f;
    float m_[2] = {-INFINITY, -INFINITY}, l_[2] = {0.f, 0.f};

    const int nt = 2 * qt + 2;
    for (int t = 0; t < nt; t++) {
        if (t + 1 < nt) {
            load_kv(sb, (t + 1) & 1, tid, b, (t + 1) * 64, h, Kh, Kl, Vh, Vl);
            CP_COMMIT();
            CP_WAIT(1);
        } else {
            CP_WAIT(0);
        }
        __syncthreads();

        const int k0 = t * 64;
        const int rowmax = q0 + wrow + 15;
        if (k0 <= rowmax) {       // warp-level causal skip
            const uint32_t kb  = sb + 2 * QBYTES + (t & 1) * KVSTG;
            const uint32_t klb = kb + 17408;
            const uint32_t vhb = kb + 34816;
            const uint32_t vlb = kb + 52224;

            float sf[8][4];
#pragma unroll
            for (int i = 0; i < 8; i++)
#pragma unroll
                for (int j = 0; j < 4; j++) sf[i][j] = 0.f;

#pragma unroll
            for (int kc = 0; kc < 8; kc++) {
#pragma unroll
                for (int g = 0; g < 4; g++) {
                    const uint32_t off = (g * 16 + lr) * APITCH + (kc * 2 + lh) * 16;
                    uint32_t bhf[4], blf[4];
                    ldsm4(bhf, kb + off);
                    ldsm4(blf, klb + off);
#pragma unroll
                    for (int n2 = 0; n2 < 2; n2++) {
                        float* cc = sf[g * 2 + n2];
                        mma16816(cc, qfh[kc], bhf[n2], bhf[n2 + 2]);
                        mma16816(cc, qfh[kc], blf[n2], blf[n2 + 2]);
                        mma16816(cc, qfl[kc], bhf[n2], bhf[n2 + 2]);
                    }
                }
            }

            // causal mask (only tiles straddling the diagonal)
            if (k0 + 63 > q0 + wrow) {
#pragma unroll
                for (int g8 = 0; g8 < 8; g8++)
#pragma unroll
                    for (int c = 0; c < 4; c++) {
                        const int key = k0 + g8 * 8 + tig * 2 + (c & 1);
                        const int row = q0 + wrow + gid + ((c >> 1) * 8);
                        if (key > row) sf[g8][c] = -1e30f;
                    }
            }

            // online softmax (rows gid and gid+8; quad lanes share a row)
#pragma unroll
            for (int r = 0; r < 2; r++) {
                float tm = -1e30f;
#pragma unroll
                for (int g8 = 0; g8 < 8; g8++)
                    tm = fmaxf(tm, fmaxf(sf[g8][r * 2], sf[g8][r * 2 + 1]));
                tm = fmaxf(tm, __shfl_xor_sync(0xffffffffu, tm, 1));
                tm = fmaxf(tm, __shfl_xor_sync(0xffffffffu, tm, 2));
                const float nm = fmaxf(m_[r], tm);
                const float fac = __expf(m_[r] - nm);
                m_[r] = nm;
                float rs = 0.f;
#pragma unroll
                for (int g8 = 0; g8 < 8; g8++) {
                    const float p0 = __expf(sf[g8][r * 2] - nm);
                    const float p1 = __expf(sf[g8][r * 2 + 1] - nm);
                    sf[g8][r * 2] = p0; sf[g8][r * 2 + 1] = p1;
                    rs += p0 + p1;
                }
                rs += __shfl_xor_sync(0xffffffffu, rs, 1);
                rs += __shfl_xor_sync(0xffffffffu, rs, 2);
                l_[r] = l_[r] * fac + rs;
#pragma unroll
                for (int n16 = 0; n16 < 16; n16++) {
                    oacc[n16][r * 2] *= fac;
                    oacc[n16][r * 2 + 1] *= fac;
                }
            }

            // P (hi/lo) x V (hi/lo), 3 products
#pragma unroll
            for (int kc2 = 0; kc2 < 4; kc2++) {
                uint32_t ph[4], pl[4];
#pragma unroll
                for (int q = 0; q < 4; q++) {
                    const float a = sf[2 * kc2 + (q >> 1)][(q & 1) * 2];
                    const float bfv = sf[2 * kc2 + (q >> 1)][(q & 1) * 2 + 1];
                    __nv_bfloat162 hb, lb;
                    split2(a, bfv, hb, lb);
                    ph[q] = *(uint32_t*)&hb;
                    pl[q] = *(uint32_t*)&lb;
                }
#pragma unroll
                for (int vt = 0; vt < 8; vt++) {
                    const uint32_t off = (kc2 * 16 + lr) * APITCH + (vt * 16 + lh * 8) * 2;
                    uint32_t vhf[4], vlf[4];
                    ldsm4t(vhf, vhb + off);
                    ldsm4t(vlf, vlb + off);
                    float* c0 = oacc[vt * 2];
                    float* c1 = oacc[vt * 2 + 1];
                    mma16816(c0, ph, vhf[0], vhf[1]);
                    mma16816(c1, ph, vhf[2], vhf[3]);
                    mma16816(c0, pl, vhf[0], vhf[1]);
                    mma16816(c1, pl, vhf[2], vhf[3]);
                    mma16816(c0, ph, vlf[0], vlf[1]);
                    mma16816(c1, ph, vlf[2], vlf[3]);
                }
            }
        }
        __syncthreads();   // protect stage reuse
    }

    // Epilogue: normalize, split to bf16 hi/lo
    const float inv0 = 1.f / l_[0];
    const float inv1 = 1.f / l_[1];
#pragma unroll
    for (int n16 = 0; n16 < 16; n16++) {
#pragma unroll
        for (int r = 0; r < 2; r++) {
            const float inv = r ? inv1 : inv0;
            const int row = q0 + wrow + gid + r * 8;
            const int col = n16 * 8 + tig * 2;
            const float f0 = oacc[n16][r * 2] * inv;
            const float f1 = oacc[n16][r * 2 + 1] * inv;
            __nv_bfloat162 hb, lb;
            split2(f0, f1, hb, lb);
            const size_t g = (size_t)(b * LL + row) * DD + h * DHd + col;
            *(__nv_bfloat162*)(Oh + g) = hb;
            *(__nv_bfloat162*)(Ol + g) = lb;
        }
    }
}

// ---------------------------------------------------------------------------
extern "C" void kernel_launch(void* const* d_in, const int* in_sizes, int n_in,
                              void* d_out, int out_size)
{
    const float* x    = (const float*)d_in[0];
    const float* cosb = (const float*)d_in[2];
    const float* sinb = (const float*)d_in[3];
    const float* wq   = (const float*)d_in[4];
    const float* wk   = (const float*)d_in[5];
    const float* wv   = (const float*)d_in[6];
    const float* wo   = (const float*)d_in[7];
    float* out = (float*)d_out;

    __nv_bfloat16 *ah, *al, *wh, *wl, *qh, *ql, *kh, *kl, *vh, *vl, *oh, *ol;
    cudaGetSymbolAddress((void**)&ah, g_ah);
    cudaGetSymbolAddress((void**)&al, g_al);
    cudaGetSymbolAddress((void**)&wh, g_wh);
    cudaGetSymbolAddress((void**)&wl, g_wl);
    cudaGetSymbolAddress((void**)&qh, g_qh);
    cudaGetSymbolAddress((void**)&ql, g_ql);
    cudaGetSymbolAddress((void**)&kh, g_kh);
    cudaGetSymbolAddress((void**)&kl, g_kl);
    cudaGetSymbolAddress((void**)&vh, g_vh);
    cudaGetSymbolAddress((void**)&vl, g_vl);
    cudaGetSymbolAddress((void**)&oh, g_oh);
    cudaGetSymbolAddress((void**)&ol, g_ol);

    const int n4x = MM * DD / 4;
    const int n4w = DD * DD / 4;
    const int SL = DD * DD;

    split_bf16<<<n4x / 256, 256>>>(x,  ah, al, n4x);
    split_bf16<<<n4w / 256, 256>>>(wq, wh + 0 * SL, wl + 0 * SL, n4w);
    split_bf16<<<n4w / 256, 256>>>(wk, wh + 1 * SL, wl + 1 * SL, n4w);
    split_bf16<<<n4w / 256, 256>>>(wv, wh + 2 * SL, wl + 2 * SL, n4w);
    split_bf16<<<n4w / 256, 256>>>(wo, wh + 3 * SL, wl + 3 * SL, n4w);

    cudaFuncSetAttribute(gemm_mma, cudaFuncAttributeMaxDynamicSharedMemorySize, GSMEM);
    cudaFuncSetAttribute(attn_mma, cudaFuncAttributeMaxDynamicSharedMemorySize, ASMEM);

    dim3 gg(DD / 128, MM / 128);  // (16, 32)
    gemm_mma<<<gg, 256, GSMEM>>>(ah, al, wh + 0 * SL, wl + 0 * SL,
                                 nullptr, qh, ql, cosb, sinb, 2);
    gemm_mma<<<gg, 256, GSMEM>>>(ah, al, wh + 1 * SL, wl + 1 * SL,
                                 nullptr, kh, kl, cosb, sinb, 1);
    gemm_mma<<<gg, 256, GSMEM>>>(ah, al, wh + 2 * SL, wl + 2 * SL,
                                 nullptr, vh, vl, cosb, sinb, 3);

    attn_mma<<<dim3(LL / 128, Bb * HH), 256, ASMEM>>>(qh, ql, kh, kl, vh, vl, oh, ol);

    gemm_mma<<<gg, 256, GSMEM>>>(oh, ol, wh + 3 * SL, wl + 3 * SL,
                                 out, nullptr, nullptr, cosb, sinb, 0);
}

// round 10
// speedup vs baseline: 2.7164x; 1.0012x over previous
#include <cuda_runtime.h>
#include <cuda_bf16.h>
#include <math.h>
#include <stdint.h>

#define Bb 2
#define LL 2048
#define DD 2048
#define HH 16
#define DHd 128
#define MM (Bb*LL)   // 4096

// Scratch (allocation-free), all bf16 hi/lo pairs
__device__ __nv_bfloat16 g_ah[MM * DD];
__device__ __nv_bfloat16 g_al[MM * DD];
__device__ __nv_bfloat16 g_wh[4 * DD * DD];
__device__ __nv_bfloat16 g_wl[4 * DD * DD];
__device__ __nv_bfloat16 g_qh[MM * DD];
__device__ __nv_bfloat16 g_ql[MM * DD];
__device__ __nv_bfloat16 g_kh[MM * DD];
__device__ __nv_bfloat16 g_kl[MM * DD];
__device__ __nv_bfloat16 g_vh[MM * DD];
__device__ __nv_bfloat16 g_vl[MM * DD];
__device__ __nv_bfloat16 g_oh[MM * DD];
__device__ __nv_bfloat16 g_ol[MM * DD];

// ---------------------------------------------------------------------------
// PTX helpers (non-'a' target: mma.sync / ldmatrix / cp.async)
// ---------------------------------------------------------------------------
__device__ __forceinline__ uint32_t s2u(const void* p) {
    uint32_t a;
    asm("{ .reg .u64 t; cvta.to.shared.u64 t, %1; cvt.u32.u64 %0, t; }"
        : "=r"(a) : "l"(p));
    return a;
}
__device__ __forceinline__ void cp16(uint32_t so, const void* g) {
    asm volatile("cp.async.cg.shared.global [%0], [%1], 16;" :: "r"(so), "l"(g));
}
#define CP_COMMIT() asm volatile("cp.async.commit_group;" ::: "memory")
#define CP_WAIT(n)  asm volatile("cp.async.wait_group %0;" :: "n"(n) : "memory")

__device__ __forceinline__ void ldsm4(uint32_t* d, uint32_t a) {
    asm volatile("ldmatrix.sync.aligned.m8n8.x4.shared.b16 {%0,%1,%2,%3}, [%4];"
                 : "=r"(d[0]), "=r"(d[1]), "=r"(d[2]), "=r"(d[3]) : "r"(a));
}
__device__ __forceinline__ void ldsm4t(uint32_t* d, uint32_t a) {
    asm volatile("ldmatrix.sync.aligned.m8n8.x4.trans.shared.b16 {%0,%1,%2,%3}, [%4];"
                 : "=r"(d[0]), "=r"(d[1]), "=r"(d[2]), "=r"(d[3]) : "r"(a));
}
__device__ __forceinline__ void mma16816(float* c, const uint32_t* a,
                                         uint32_t b0, uint32_t b1) {
    asm volatile(
        "mma.sync.aligned.m16n8k16.row.col.f32.bf16.bf16.f32 "
        "{%0,%1,%2,%3}, {%4,%5,%6,%7}, {%8,%9}, {%0,%1,%2,%3};"
        : "+f"(c[0]), "+f"(c[1]), "+f"(c[2]), "+f"(c[3])
        : "r"(a[0]), "r"(a[1]), "r"(a[2]), "r"(a[3]), "r"(b0), "r"(b1));
}
__device__ __forceinline__ void split2(float f0, float f1,
                                       __nv_bfloat162& h, __nv_bfloat162& l) {
    h = __floats2bfloat162_rn(f0, f1);
    float2 hf = __bfloat1622float2(h);
    l = __floats2bfloat162_rn(f0 - hf.x, f1 - hf.y);
}

// ---------------------------------------------------------------------------
// Split fp32 -> bf16 hi/lo (x and weights only)
// ---------------------------------------------------------------------------
__global__ void __launch_bounds__(256) split_bf16(
    const float* __restrict__ s, __nv_bfloat16* __restrict__ h,
    __nv_bfloat16* __restrict__ l, int n4)
{
    int i = blockIdx.x * 256 + threadIdx.x;
    if (i >= n4) return;
    float4 f = ((const float4*)s)[i];
    __nv_bfloat162 h0, h1, l0, l1;
    split2(f.x, f.y, h0, l0);
    split2(f.z, f.w, h1, l1);
    ((__nv_bfloat162*)h)[2*i]   = h0;
    ((__nv_bfloat162*)h)[2*i+1] = h1;
    ((__nv_bfloat162*)l)[2*i]   = l0;
    ((__nv_bfloat162*)l)[2*i+1] = l1;
}

// ---------------------------------------------------------------------------
// GEMM: C = A*W^T, bf16 hi/lo 3-product, fp32 accum.  BM=BN=128, BK=32.
// 3-stage cp.async pipeline, ONE __syncthreads per k-iter.
// mode: 0 fp32 store -> Cf;  1 RoPE+split -> Ch/Cl;  2 RoPE+scale+split;  3 split
// ---------------------------------------------------------------------------
#define ROWB 80
#define TILEB (128 * ROWB)
#define STGB  (4 * TILEB)           // 40960
#define GSMEM (3 * STGB)            // 122880

__device__ __forceinline__ void load_stage(
    uint32_t sb, int stage, int tid, int m0, int n0, int kt,
    const __nv_bfloat16* __restrict__ Ah, const __nv_bfloat16* __restrict__ Al,
    const __nv_bfloat16* __restrict__ Wh, const __nv_bfloat16* __restrict__ Wl)
{
    const uint32_t base = sb + stage * STGB;
    const int k0 = kt * 32;
#pragma unroll
    for (int j = 0; j < 2; j++) {
        const int idx = tid + j * 256;
        const int r = idx >> 2, c16 = idx & 3;
        const uint32_t so = r * ROWB + c16 * 16;
        const size_t ga = (size_t)(m0 + r) * DD + k0 + c16 * 8;
        const size_t gw = (size_t)(n0 + r) * DD + k0 + c16 * 8;
        cp16(base + so,             Ah + ga);
        cp16(base + TILEB + so,     Al + ga);
        cp16(base + 2 * TILEB + so, Wh + gw);
        cp16(base + 3 * TILEB + so, Wl + gw);
    }
}

__global__ void __launch_bounds__(256) gemm_mma(
    const __nv_bfloat16* __restrict__ Ah, const __nv_bfloat16* __restrict__ Al,
    const __nv_bfloat16* __restrict__ Wh, const __nv_bfloat16* __restrict__ Wl,
    float* __restrict__ Cf, __nv_bfloat16* __restrict__ Ch,
    __nv_bfloat16* __restrict__ Cl, const float* __restrict__ cosb,
    const float* __restrict__ sinb, int mode)
{
    extern __shared__ char sm[];
    const uint32_t sb = s2u(sm);
    const int tid = threadIdx.x, wid = tid >> 5, lid = tid & 31;
    const int m0 = blockIdx.y * 128, n0 = blockIdx.x * 128;
    const int m0w = (wid & 3) * 32;
    const int n0w = (wid >> 2) * 64;

    float acc[2][8][4];
#pragma unroll
    for (int a = 0; a < 2; a++)
#pragma unroll
        for (int b = 0; b < 8; b++)
#pragma unroll
            for (int c = 0; c < 4; c++) acc[a][b][c] = 0.f;

    load_stage(sb, 0, tid, m0, n0, 0, Ah, Al, Wh, Wl);
    CP_COMMIT();
    load_stage(sb, 1, tid, m0, n0, 1, Ah, Al, Wh, Wl);
    CP_COMMIT();

    const int lr = lid & 15, lh = lid >> 4;

    for (int kt = 0; kt < 64; kt++) {
        if (kt + 1 < 64) { CP_WAIT(1); } else { CP_WAIT(0); }
        __syncthreads();
        if (kt + 2 < 64) {
            load_stage(sb, (kt + 2) % 3, tid, m0, n0, kt + 2, Ah, Al, Wh, Wl);
            CP_COMMIT();
        }
        const uint32_t bA  = sb + (kt % 3) * STGB;
        const uint32_t bAl = bA + TILEB;
        const uint32_t bWh = bA + 2 * TILEB;
        const uint32_t bWl = bA + 3 * TILEB;

#pragma unroll
        for (int kk = 0; kk < 2; kk++) {
            const int c16 = kk * 2 + lh;
            uint32_t ah[2][4], al[2][4];
#pragma unroll
            for (int mt = 0; mt < 2; mt++) {
                const int r = m0w + mt * 16 + lr;
                const uint32_t off = r * ROWB + c16 * 16;
                ldsm4(ah[mt], bA + off);
                ldsm4(al[mt], bAl + off);
            }
#pragma unroll
            for (int g = 0; g < 4; g++) {
                const int rn = n0w + g * 16 + lr;
                const uint32_t offb = rn * ROWB + c16 * 16;
                uint32_t bh[4], bl[4];
                ldsm4(bh, bWh + offb);
                ldsm4(bl, bWl + offb);
#pragma unroll
                for (int mt = 0; mt < 2; mt++) {
#pragma unroll
                    for (int nt = 0; nt < 2; nt++) {
                        float* cc = acc[mt][g * 2 + nt];
                        mma16816(cc, ah[mt], bh[nt], bh[nt + 2]);
                        mma16816(cc, ah[mt], bl[nt], bl[nt + 2]);
                        mma16816(cc, al[mt], bh[nt], bh[nt + 2]);
                    }
                }
            }
        }
    }

    // Epilogue
    const int gid = lid >> 2, tig = lid & 3;
#pragma unroll
    for (int mt = 0; mt < 2; mt++) {
#pragma unroll
        for (int nt8 = 0; nt8 < 8; nt8++) {
            const float* cc = acc[mt][nt8];
            const int gn = n0 + n0w + nt8 * 8 + tig * 2;
#pragma unroll
            for (int hrow = 0; hrow < 2; hrow++) {
                const int m = m0 + m0w + mt * 16 + gid + hrow * 8;
                float v0 = cc[hrow * 2], v1 = cc[hrow * 2 + 1];
                if (mode == 1 || mode == 2) {
                    const int lrow = m & (LL - 1);
                    const int ip = (gn & (DHd - 1)) >> 1;
                    const float co = cosb[lrow * 64 + ip];
                    const float si = sinb[lrow * 64 + ip];
                    const float t0 = v0 * co - v1 * si;
                    const float t1 = v0 * si + v1 * co;
                    v0 = t0; v1 = t1;
                    if (mode == 2) { v0 *= 0.08838834764831845f; v1 *= 0.08838834764831845f; }
                }
                const size_t gidx = (size_t)m * DD + gn;
                if (mode == 0) {
                    *(float2*)(Cf + gidx) = make_float2(v0, v1);
                } else {
                    __nv_bfloat162 hb, lb;
                    split2(v0, v1, hb, lb);
                    *(__nv_bfloat162*)(Ch + gidx) = hb;
                    *(__nv_bfloat162*)(Cl + gidx) = lb;
                }
            }
        }
    }
}

// ---------------------------------------------------------------------------
// Flash attention, mma.sync, hi/lo 3-product for S and PV.
// CTA: 128 q rows, 8 warps x 16 rows. 64-key tiles, double-buffered cp.async.
// smem: Qh/Ql (128x272B each) + 2 stages of {Kh,Kl,Vh,Vl} (64x272B each).
// ---------------------------------------------------------------------------
#define APITCH 272
#define QBYTES (128 * APITCH)        // 34816
#define KVSTG  (4 * 64 * APITCH)     // 69632
#define ASMEM  (2 * QBYTES + 2 * KVSTG)  // 208896

__device__ __forceinline__ void load_kv(
    uint32_t sb, int stage, int tid, int b, int k0, int h,
    const __nv_bfloat16* __restrict__ Kh, const __nv_bfloat16* __restrict__ Kl,
    const __nv_bfloat16* __restrict__ Vh, const __nv_bfloat16* __restrict__ Vl)
{
    const uint32_t base = sb + 2 * QBYTES + stage * KVSTG;
#pragma unroll
    for (int j = 0; j < 4; j++) {
        const int i = tid + j * 256;
        const int r = i >> 4, c = i & 15;
        const uint32_t off = r * APITCH + c * 16;
        const size_t g = (size_t)(b * LL + k0 + r) * DD + h * DHd + c * 8;
        cp16(base + off,             Kh + g);
        cp16(base + 17408 + off,     Kl + g);
        cp16(base + 34816 + off,     Vh + g);
        cp16(base + 52224 + off,     Vl + g);
    }
}

__global__ void __launch_bounds__(256, 1) attn_mma(
    const __nv_bfloat16* __restrict__ Qh, const __nv_bfloat16* __restrict__ Ql,
    const __nv_bfloat16* __restrict__ Kh, const __nv_bfloat16* __restrict__ Kl,
    const __nv_bfloat16* __restrict__ Vh, const __nv_bfloat16* __restrict__ Vl,
    __nv_bfloat16* __restrict__ Oh, __nv_bfloat16* __restrict__ Ol)
{
    extern __shared__ char sm[];
    const uint32_t sb = s2u(sm);
    const int tid = threadIdx.x, wid = tid >> 5, lid = tid & 31;
    const int lr = lid & 15, lh = lid >> 4;
    const int gid = lid >> 2, tig = lid & 3;
    const int qt = blockIdx.x, bh = blockIdx.y;
    const int b = bh >> 4, h = bh & 15;
    const int q0 = qt * 128;

    // Q tiles (hi/lo) via cp.async  (group 0)
#pragma unroll
    for (int j = 0; j < 8; j++) {
        const int i = tid + j * 256;
        const int r = i >> 4, c = i & 15;
        const size_t g = (size_t)(b * LL + q0 + r) * DD + h * DHd + c * 8;
        const uint32_t off = r * APITCH + c * 16;
        cp16(sb + off, Qh + g);
        cp16(sb + QBYTES + off, Ql + g);
    }
    CP_COMMIT();
    load_kv(sb, 0, tid, b, 0, h, Kh, Kl, Vh, Vl);   // group 1
    CP_COMMIT();

    CP_WAIT(1);          // Q ready
    __syncthreads();

    // Build Q fragments (held in registers for the whole kernel)
    uint32_t qfh[8][4], qfl[8][4];
    const int wrow = wid * 16;
#pragma unroll
    for (int kc = 0; kc < 8; kc++) {
        const uint32_t off = (wrow + lr) * APITCH + (kc * 2 + lh) * 16;
        ldsm4(qfh[kc], sb + off);
        ldsm4(qfl[kc], sb + QBYTES + off);
    }

    float oacc[16][4];
#pragma unroll
    for (int i = 0; i < 16; i++)
#pragma unroll
        for (int j = 0; j < 4; j++) oacc[i][j] = 0.f;
    float m_[2] = {-INFINITY, -INFINITY}, l_[2] = {0.f, 0.f};

    const int nt = 2 * qt + 2;
    for (int t = 0; t < nt; t++) {
        if (t + 1 < nt) {
            load_kv(sb, (t + 1) & 1, tid, b, (t + 1) * 64, h, Kh, Kl, Vh, Vl);
            CP_COMMIT();
            CP_WAIT(1);
        } else {
            CP_WAIT(0);
        }
        __syncthreads();

        const int k0 = t * 64;
        const int rowmax = q0 + wrow + 15;
        if (k0 <= rowmax) {       // warp-level causal skip
            const uint32_t kb  = sb + 2 * QBYTES + (t & 1) * KVSTG;
            const uint32_t klb = kb + 17408;
            const uint32_t vhb = kb + 34816;
            const uint32_t vlb = kb + 52224;

            float sf[8][4];
#pragma unroll
            for (int i = 0; i < 8; i++)
#pragma unroll
                for (int j = 0; j < 4; j++) sf[i][j] = 0.f;

#pragma unroll
            for (int kc = 0; kc < 8; kc++) {
#pragma unroll
                for (int g = 0; g < 4; g++) {
                    const uint32_t off = (g * 16 + lr) * APITCH + (kc * 2 + lh) * 16;
                    uint32_t bhf[4], blf[4];
                    ldsm4(bhf, kb + off);
                    ldsm4(blf, klb + off);
#pragma unroll
                    for (int n2 = 0; n2 < 2; n2++) {
                        float* cc = sf[g * 2 + n2];
                        mma16816(cc, qfh[kc], bhf[n2], bhf[n2 + 2]);
                        mma16816(cc, qfh[kc], blf[n2], blf[n2 + 2]);
                        mma16816(cc, qfl[kc], bhf[n2], bhf[n2 + 2]);
                    }
                }
            }

            // causal mask (only tiles straddling the diagonal)
            if (k0 + 63 > q0 + wrow) {
#pragma unroll
                for (int g8 = 0; g8 < 8; g8++)
#pragma unroll
                    for (int c = 0; c < 4; c++) {
                        const int key = k0 + g8 * 8 + tig * 2 + (c & 1);
                        const int row = q0 + wrow + gid + ((c >> 1) * 8);
                        if (key > row) sf[g8][c] = -1e30f;
                    }
            }

            // online softmax (rows gid and gid+8; quad lanes share a row)
#pragma unroll
            for (int r = 0; r < 2; r++) {
                float tm = -1e30f;
#pragma unroll
                for (int g8 = 0; g8 < 8; g8++)
                    tm = fmaxf(tm, fmaxf(sf[g8][r * 2], sf[g8][r * 2 + 1]));
                tm = fmaxf(tm, __shfl_xor_sync(0xffffffffu, tm, 1));
                tm = fmaxf(tm, __shfl_xor_sync(0xffffffffu, tm, 2));
                const float nm = fmaxf(m_[r], tm);
                const float fac = __expf(m_[r] - nm);
                m_[r] = nm;
                float rs = 0.f;
#pragma unroll
                for (int g8 = 0; g8 < 8; g8++) {
                    const float p0 = __expf(sf[g8][r * 2] - nm);
                    const float p1 = __expf(sf[g8][r * 2 + 1] - nm);
                    sf[g8][r * 2] = p0; sf[g8][r * 2 + 1] = p1;
                    rs += p0 + p1;
                }
                rs += __shfl_xor_sync(0xffffffffu, rs, 1);
                rs += __shfl_xor_sync(0xffffffffu, rs, 2);
                l_[r] = l_[r] * fac + rs;
#pragma unroll
                for (int n16 = 0; n16 < 16; n16++) {
                    oacc[n16][r * 2] *= fac;
                    oacc[n16][r * 2 + 1] *= fac;
                }
            }

            // P (hi/lo) x V (hi/lo), 3 products
#pragma unroll
            for (int kc2 = 0; kc2 < 4; kc2++) {
                uint32_t ph[4], pl[4];
#pragma unroll
                for (int q = 0; q < 4; q++) {
                    const float a = sf[2 * kc2 + (q >> 1)][(q & 1) * 2];
                    const float bfv = sf[2 * kc2 + (q >> 1)][(q & 1) * 2 + 1];
                    __nv_bfloat162 hb, lb;
                    split2(a, bfv, hb, lb);
                    ph[q] = *(uint32_t*)&hb;
                    pl[q] = *(uint32_t*)&lb;
                }
#pragma unroll
                for (int vt = 0; vt < 8; vt++) {
                    const uint32_t off = (kc2 * 16 + lr) * APITCH + (vt * 16 + lh * 8) * 2;
                    uint32_t vhf[4], vlf[4];
                    ldsm4t(vhf, vhb + off);
                    ldsm4t(vlf, vlb + off);
                    float* c0 = oacc[vt * 2];
                    float* c1 = oacc[vt * 2 + 1];
                    mma16816(c0, ph, vhf[0], vhf[1]);
                    mma16816(c1, ph, vhf[2], vhf[3]);
                    mma16816(c0, pl, vhf[0], vhf[1]);
                    mma16816(c1, pl, vhf[2], vhf[3]);
                    mma16816(c0, ph, vlf[0], vlf[1]);
                    mma16816(c1, ph, vlf[2], vlf[3]);
                }
            }
        }
        __syncthreads();   // protect stage reuse
    }

    // Epilogue: normalize, split to bf16 hi/lo
    const float inv0 = 1.f / l_[0];
    const float inv1 = 1.f / l_[1];
#pragma unroll
    for (int n16 = 0; n16 < 16; n16++) {
#pragma unroll
        for (int r = 0; r < 2; r++) {
            const float inv = r ? inv1 : inv0;
            const int row = q0 + wrow + gid + r * 8;
            const int col = n16 * 8 + tig * 2;
            const float f0 = oacc[n16][r * 2] * inv;
            const float f1 = oacc[n16][r * 2 + 1] * inv;
            __nv_bfloat162 hb, lb;
            split2(f0, f1, hb, lb);
            const size_t g = (size_t)(b * LL + row) * DD + h * DHd + col;
            *(__nv_bfloat162*)(Oh + g) = hb;
            *(__nv_bfloat162*)(Ol + g) = lb;
        }
    }
}

// ---------------------------------------------------------------------------
extern "C" void kernel_launch(void* const* d_in, const int* in_sizes, int n_in,
                              void* d_out, int out_size)
{
    const float* x    = (const float*)d_in[0];
    const float* cosb = (const float*)d_in[2];
    const float* sinb = (const float*)d_in[3];
    const float* wq   = (const float*)d_in[4];
    const float* wk   = (const float*)d_in[5];
    const float* wv   = (const float*)d_in[6];
    const float* wo   = (const float*)d_in[7];
    float* out = (float*)d_out;

    __nv_bfloat16 *ah, *al, *wh, *wl, *qh, *ql, *kh, *kl, *vh, *vl, *oh, *ol;
    cudaGetSymbolAddress((void**)&ah, g_ah);
    cudaGetSymbolAddress((void**)&al, g_al);
    cudaGetSymbolAddress((void**)&wh, g_wh);
    cudaGetSymbolAddress((void**)&wl, g_wl);
    cudaGetSymbolAddress((void**)&qh, g_qh);
    cudaGetSymbolAddress((void**)&ql, g_ql);
    cudaGetSymbolAddress((void**)&kh, g_kh);
    cudaGetSymbolAddress((void**)&kl, g_kl);
    cudaGetSymbolAddress((void**)&vh, g_vh);
    cudaGetSymbolAddress((void**)&vl, g_vl);
    cudaGetSymbolAddress((void**)&oh, g_oh);
    cudaGetSymbolAddress((void**)&ol, g_ol);

    const int n4x = MM * DD / 4;
    const int n4w = DD * DD / 4;
    const int SL = DD * DD;

    split_bf16<<<n4x / 256, 256>>>(x,  ah, al, n4x);
    split_bf16<<<n4w / 256, 256>>>(wq, wh + 0 * SL, wl + 0 * SL, n4w);
    split_bf16<<<n4w / 256, 256>>>(wk, wh + 1 * SL, wl + 1 * SL, n4w);
    split_bf16<<<n4w / 256, 256>>>(wv, wh + 2 * SL, wl + 2 * SL, n4w);
    split_bf16<<<n4w / 256, 256>>>(wo, wh + 3 * SL, wl + 3 * SL, n4w);

    cudaFuncSetAttribute(gemm_mma, cudaFuncAttributeMaxDynamicSharedMemorySize, GSMEM);
    cudaFuncSetAttribute(attn_mma, cudaFuncAttributeMaxDynamicSharedMemorySize, ASMEM);

    dim3 gg(DD / 128, MM / 128);  // (16, 32)
    gemm_mma<<<gg, 256, GSMEM>>>(ah, al, wh + 0 * SL, wl + 0 * SL,
                                 nullptr, qh, ql, cosb, sinb, 2);
    gemm_mma<<<gg, 256, GSMEM>>>(ah, al, wh + 1 * SL, wl + 1 * SL,
                                 nullptr, kh, kl, cosb, sinb, 1);
    gemm_mma<<<gg, 256, GSMEM>>>(ah, al, wh + 2 * SL, wl + 2 * SL,
                                 nullptr, vh, vl, cosb, sinb, 3);

    attn_mma<<<dim3(LL / 128, Bb * HH), 256, ASMEM>>>(qh, ql, kh, kl, vh, vl, oh, ol);

    gemm_mma<<<gg, 256, GSMEM>>>(oh, ol, wh + 3 * SL, wl + 3 * SL,
                                 out, nullptr, nullptr, cosb, sinb, 0);
}

// round 11
// speedup vs baseline: 3.1232x; 1.1497x over previous
#include <cuda_runtime.h>
#include <cuda_bf16.h>
#include <math.h>
#include <stdint.h>

#define Bb 2
#define LL 2048
#define DD 2048
#define HH 16
#define DHd 128
#define MM (Bb*LL)   // 4096
#define SLW (DD*DD)

// Scratch (allocation-free), all bf16 hi/lo pairs
__device__ __nv_bfloat16 g_ah[MM * DD];
__device__ __nv_bfloat16 g_al[MM * DD];
__device__ __nv_bfloat16 g_wh[4 * SLW];
__device__ __nv_bfloat16 g_wl[4 * SLW];
__device__ __nv_bfloat16 g_qh[MM * DD];
__device__ __nv_bfloat16 g_ql[MM * DD];
__device__ __nv_bfloat16 g_kh[MM * DD];
__device__ __nv_bfloat16 g_kl[MM * DD];
__device__ __nv_bfloat16 g_vh[MM * DD];
__device__ __nv_bfloat16 g_vl[MM * DD];
__device__ __nv_bfloat16 g_oh[MM * DD];
__device__ __nv_bfloat16 g_ol[MM * DD];

// ---------------------------------------------------------------------------
// PTX helpers (non-'a' target: mma.sync / ldmatrix / cp.async)
// ---------------------------------------------------------------------------
__device__ __forceinline__ uint32_t s2u(const void* p) {
    uint32_t a;
    asm("{ .reg .u64 t; cvta.to.shared.u64 t, %1; cvt.u32.u64 %0, t; }"
        : "=r"(a) : "l"(p));
    return a;
}
__device__ __forceinline__ void cp16(uint32_t so, const void* g) {
    asm volatile("cp.async.cg.shared.global [%0], [%1], 16;" :: "r"(so), "l"(g));
}
#define CP_COMMIT() asm volatile("cp.async.commit_group;" ::: "memory")
#define CP_WAIT(n)  asm volatile("cp.async.wait_group %0;" :: "n"(n) : "memory")

__device__ __forceinline__ void ldsm4(uint32_t* d, uint32_t a) {
    asm volatile("ldmatrix.sync.aligned.m8n8.x4.shared.b16 {%0,%1,%2,%3}, [%4];"
                 : "=r"(d[0]), "=r"(d[1]), "=r"(d[2]), "=r"(d[3]) : "r"(a));
}
__device__ __forceinline__ void ldsm4t(uint32_t* d, uint32_t a) {
    asm volatile("ldmatrix.sync.aligned.m8n8.x4.trans.shared.b16 {%0,%1,%2,%3}, [%4];"
                 : "=r"(d[0]), "=r"(d[1]), "=r"(d[2]), "=r"(d[3]) : "r"(a));
}
__device__ __forceinline__ void mma16816(float* c, const uint32_t* a,
                                         uint32_t b0, uint32_t b1) {
    asm volatile(
        "mma.sync.aligned.m16n8k16.row.col.f32.bf16.bf16.f32 "
        "{%0,%1,%2,%3}, {%4,%5,%6,%7}, {%8,%9}, {%0,%1,%2,%3};"
        : "+f"(c[0]), "+f"(c[1]), "+f"(c[2]), "+f"(c[3])
        : "r"(a[0]), "r"(a[1]), "r"(a[2]), "r"(a[3]), "r"(b0), "r"(b1));
}
__device__ __forceinline__ void split2(float f0, float f1,
                                       __nv_bfloat162& h, __nv_bfloat162& l) {
    h = __floats2bfloat162_rn(f0, f1);
    float2 hf = __bfloat1622float2(h);
    l = __floats2bfloat162_rn(f0 - hf.x, f1 - hf.y);
}

// ---------------------------------------------------------------------------
// Splits: fp32 -> bf16 hi/lo.  x separately; 4 weights merged (grid.y = 4).
// ---------------------------------------------------------------------------
__global__ void __launch_bounds__(256) split_bf16(
    const float* __restrict__ s, __nv_bfloat16* __restrict__ h,
    __nv_bfloat16* __restrict__ l)
{
    const int i = blockIdx.x * 256 + threadIdx.x;
    float4 f = ((const float4*)s)[i];
    __nv_bfloat162 h0, h1, l0, l1;
    split2(f.x, f.y, h0, l0);
    split2(f.z, f.w, h1, l1);
    ((__nv_bfloat162*)h)[2*i]   = h0;
    ((__nv_bfloat162*)h)[2*i+1] = h1;
    ((__nv_bfloat162*)l)[2*i]   = l0;
    ((__nv_bfloat162*)l)[2*i+1] = l1;
}

__global__ void __launch_bounds__(256) split_w4(
    const float* __restrict__ w0, const float* __restrict__ w1,
    const float* __restrict__ w2, const float* __restrict__ w3,
    __nv_bfloat16* __restrict__ h, __nv_bfloat16* __restrict__ l)
{
    const int z = blockIdx.y;
    const float* s = (z == 0) ? w0 : (z == 1) ? w1 : (z == 2) ? w2 : w3;
    const int i = blockIdx.x * 256 + threadIdx.x;
    float4 f = ((const float4*)s)[i];
    __nv_bfloat162 h0, h1, l0, l1;
    split2(f.x, f.y, h0, l0);
    split2(f.z, f.w, h1, l1);
    const size_t o = (size_t)z * (SLW / 2) + 2 * i;
    ((__nv_bfloat162*)h)[o]     = h0;
    ((__nv_bfloat162*)h)[o + 1] = h1;
    ((__nv_bfloat162*)l)[o]     = l0;
    ((__nv_bfloat162*)l)[o + 1] = l1;
}

// ---------------------------------------------------------------------------
// GEMM: C = A*W^T, bf16 hi/lo 3-product, fp32 accum.
// BM=128 BN=64 BK=32. 256 thr (8 warps: 4m x 2n, warp tile 32x32).
// 2 CTAs/SM (smem 92160, regs <=128). 3-stage cp.async pipeline.
// qkv=1: grid.z in {0,1,2} selects {Q: RoPE+scale, K: RoPE, V: plain} -> bf16 pairs.
// qkv=0: fp32 store -> Cf.
// ---------------------------------------------------------------------------
#define ROWB 80
#define AT64 (128 * ROWB)           // 10240
#define BT64 (64 * ROWB)            // 5120
#define STG64 (2 * AT64 + 2 * BT64) // 30720
#define GSMEM (3 * STG64)           // 92160

__device__ __forceinline__ void load_stage64(
    uint32_t sb, int stage, int tid, int m0, int n0, int kt,
    const __nv_bfloat16* __restrict__ Ah, const __nv_bfloat16* __restrict__ Al,
    const __nv_bfloat16* __restrict__ Bh, const __nv_bfloat16* __restrict__ Bl)
{
    const uint32_t base = sb + stage * STG64;
    const int k0 = kt * 32;
#pragma unroll
    for (int j = 0; j < 2; j++) {
        const int idx = tid + j * 256;
        const int r = idx >> 2, c16 = idx & 3;
        const uint32_t so = r * ROWB + c16 * 16;
        const size_t ga = (size_t)(m0 + r) * DD + k0 + c16 * 8;
        cp16(base + so,        Ah + ga);
        cp16(base + AT64 + so, Al + ga);
    }
    {
        const int r = tid >> 2, c16 = tid & 3;
        const uint32_t so = r * ROWB + c16 * 16;
        const size_t gw = (size_t)(n0 + r) * DD + k0 + c16 * 8;
        cp16(base + 2 * AT64 + so,        Bh + gw);
        cp16(base + 2 * AT64 + BT64 + so, Bl + gw);
    }
}

__global__ void __launch_bounds__(256, 2) gemm64(
    const __nv_bfloat16* __restrict__ Ah, const __nv_bfloat16* __restrict__ Al,
    const __nv_bfloat16* __restrict__ Wh, const __nv_bfloat16* __restrict__ Wl,
    float* __restrict__ Cf,
    __nv_bfloat16* __restrict__ qh, __nv_bfloat16* __restrict__ ql,
    __nv_bfloat16* __restrict__ kh, __nv_bfloat16* __restrict__ kl,
    __nv_bfloat16* __restrict__ vh, __nv_bfloat16* __restrict__ vl,
    const float* __restrict__ cosb, const float* __restrict__ sinb, int qkv)
{
    extern __shared__ char sm[];
    const uint32_t sb = s2u(sm);
    const int tid = threadIdx.x, wid = tid >> 5, lid = tid & 31;
    const int lr = lid & 15, lh = lid >> 4;
    const int m0 = blockIdx.y * 128, n0 = blockIdx.x * 64;
    const int z = blockIdx.z;
    const int m0w = (wid & 3) * 32;
    const int n0w = (wid >> 2) * 32;

    const __nv_bfloat16* Bh = Wh + (size_t)(qkv ? z : 0) * SLW;
    const __nv_bfloat16* Bl = Wl + (size_t)(qkv ? z : 0) * SLW;
    const int mode = qkv ? ((z == 0) ? 2 : (z == 1) ? 1 : 3) : 0;
    __nv_bfloat16 *Ch = nullptr, *Cl = nullptr;
    if (qkv) {
        if (z == 0)      { Ch = qh; Cl = ql; }
        else if (z == 1) { Ch = kh; Cl = kl; }
        else             { Ch = vh; Cl = vl; }
    }

    float acc[2][4][4];
#pragma unroll
    for (int a = 0; a < 2; a++)
#pragma unroll
        for (int b = 0; b < 4; b++)
#pragma unroll
            for (int c = 0; c < 4; c++) acc[a][b][c] = 0.f;

    load_stage64(sb, 0, tid, m0, n0, 0, Ah, Al, Bh, Bl);
    CP_COMMIT();
    load_stage64(sb, 1, tid, m0, n0, 1, Ah, Al, Bh, Bl);
    CP_COMMIT();

    for (int kt = 0; kt < 64; kt++) {
        if (kt + 1 < 64) { CP_WAIT(1); } else { CP_WAIT(0); }
        __syncthreads();
        if (kt + 2 < 64) {
            load_stage64(sb, (kt + 2) % 3, tid, m0, n0, kt + 2, Ah, Al, Bh, Bl);
            CP_COMMIT();
        }
        const uint32_t bA  = sb + (kt % 3) * STG64;
        const uint32_t bAl = bA + AT64;
        const uint32_t bWh = bA + 2 * AT64;
        const uint32_t bWl = bWh + BT64;

#pragma unroll
        for (int kk = 0; kk < 2; kk++) {
            const int c16 = kk * 2 + lh;
            uint32_t ahf[2][4], alf[2][4];
#pragma unroll
            for (int mt = 0; mt < 2; mt++) {
                const uint32_t off = (m0w + mt * 16 + lr) * ROWB + c16 * 16;
                ldsm4(ahf[mt], bA + off);
                ldsm4(alf[mt], bAl + off);
            }
#pragma unroll
            for (int g = 0; g < 2; g++) {
                const uint32_t offb = (n0w + g * 16 + lr) * ROWB + c16 * 16;
                uint32_t bhf[4], blf[4];
                ldsm4(bhf, bWh + offb);
                ldsm4(blf, bWl + offb);
#pragma unroll
                for (int mt = 0; mt < 2; mt++) {
#pragma unroll
                    for (int nt = 0; nt < 2; nt++) {
                        float* cc = acc[mt][g * 2 + nt];
                        mma16816(cc, ahf[mt], bhf[nt], bhf[nt + 2]);
                        mma16816(cc, ahf[mt], blf[nt], blf[nt + 2]);
                        mma16816(cc, alf[mt], bhf[nt], bhf[nt + 2]);
                    }
                }
            }
        }
    }

    // Epilogue
    const int gid = lid >> 2, tig = lid & 3;
#pragma unroll
    for (int mt = 0; mt < 2; mt++) {
#pragma unroll
        for (int ix = 0; ix < 4; ix++) {
            const float* cc = acc[mt][ix];
            const int gn = n0 + n0w + ix * 8 + tig * 2;
#pragma unroll
            for (int hrow = 0; hrow < 2; hrow++) {
                const int m = m0 + m0w + mt * 16 + gid + hrow * 8;
                float v0 = cc[hrow * 2], v1 = cc[hrow * 2 + 1];
                if (mode == 1 || mode == 2) {
                    const int lrow = m & (LL - 1);
                    const int ip = (gn & (DHd - 1)) >> 1;
                    const float co = cosb[lrow * 64 + ip];
                    const float si = sinb[lrow * 64 + ip];
                    const float t0 = v0 * co - v1 * si;
                    const float t1 = v0 * si + v1 * co;
                    v0 = t0; v1 = t1;
                    if (mode == 2) { v0 *= 0.08838834764831845f; v1 *= 0.08838834764831845f; }
                }
                const size_t gidx = (size_t)m * DD + gn;
                if (mode == 0) {
                    *(float2*)(Cf + gidx) = make_float2(v0, v1);
                } else {
                    __nv_bfloat162 hb, lb;
                    split2(v0, v1, hb, lb);
                    *(__nv_bfloat162*)(Ch + gidx) = hb;
                    *(__nv_bfloat162*)(Cl + gidx) = lb;
                }
            }
        }
    }
}

// ---------------------------------------------------------------------------
// Flash attention, mma.sync, hi/lo 3-product for S and PV.
// CTA: 128 q rows, 8 warps x 16 rows. Heavy tiles scheduled first (qt reversed).
// ---------------------------------------------------------------------------
#define APITCH 272
#define QBYTES (128 * APITCH)        // 34816
#define KVSTG  (4 * 64 * APITCH)     // 69632
#define ASMEM  (2 * QBYTES + 2 * KVSTG)  // 208896

__device__ __forceinline__ void load_kv(
    uint32_t sb, int stage, int tid, int b, int k0, int h,
    const __nv_bfloat16* __restrict__ Kh, const __nv_bfloat16* __restrict__ Kl,
    const __nv_bfloat16* __restrict__ Vh, const __nv_bfloat16* __restrict__ Vl)
{
    const uint32_t base = sb + 2 * QBYTES + stage * KVSTG;
#pragma unroll
    for (int j = 0; j < 4; j++) {
        const int i = tid + j * 256;
        const int r = i >> 4, c = i & 15;
        const uint32_t off = r * APITCH + c * 16;
        const size_t g = (size_t)(b * LL + k0 + r) * DD + h * DHd + c * 8;
        cp16(base + off,         Kh + g);
        cp16(base + 17408 + off, Kl + g);
        cp16(base + 34816 + off, Vh + g);
        cp16(base + 52224 + off, Vl + g);
    }
}

__global__ void __launch_bounds__(256, 1) attn_mma(
    const __nv_bfloat16* __restrict__ Qh, const __nv_bfloat16* __restrict__ Ql,
    const __nv_bfloat16* __restrict__ Kh, const __nv_bfloat16* __restrict__ Kl,
    const __nv_bfloat16* __restrict__ Vh, const __nv_bfloat16* __restrict__ Vl,
    __nv_bfloat16* __restrict__ Oh, __nv_bfloat16* __restrict__ Ol)
{
    extern __shared__ char sm[];
    const uint32_t sb = s2u(sm);
    const int tid = threadIdx.x, wid = tid >> 5, lid = tid & 31;
    const int lr = lid & 15, lh = lid >> 4;
    const int gid = lid >> 2, tig = lid & 3;
    const int qt = (int)gridDim.x - 1 - (int)blockIdx.x;   // heavy first
    const int bh = blockIdx.y;
    const int b = bh >> 4, h = bh & 15;
    const int q0 = qt * 128;

    // Q tiles (hi/lo) via cp.async  (group 0)
#pragma unroll
    for (int j = 0; j < 8; j++) {
        const int i = tid + j * 256;
        const int r = i >> 4, c = i & 15;
        const size_t g = (size_t)(b * LL + q0 + r) * DD + h * DHd + c * 8;
        const uint32_t off = r * APITCH + c * 16;
        cp16(sb + off, Qh + g);
        cp16(sb + QBYTES + off, Ql + g);
    }
    CP_COMMIT();
    load_kv(sb, 0, tid, b, 0, h, Kh, Kl, Vh, Vl);   // group 1
    CP_COMMIT();

    CP_WAIT(1);          // Q ready
    __syncthreads();

    uint32_t qfh[8][4], qfl[8][4];
    const int wrow = wid * 16;
#pragma unroll
    for (int kc = 0; kc < 8; kc++) {
        const uint32_t off = (wrow + lr) * APITCH + (kc * 2 + lh) * 16;
        ldsm4(qfh[kc], sb + off);
        ldsm4(qfl[kc], sb + QBYTES + off);
    }

    float oacc[16][4];
#pragma unroll
    for (int i = 0; i < 16; i++)
#pragma unroll
        for (int j = 0; j < 4; j++) oacc[i][j] = 0.f;
    float m_[2] = {-INFINITY, -INFINITY}, l_[2] = {0.f, 0.f};

    const int nt = 2 * qt + 2;
    for (int t = 0; t < nt; t++) {
        if (t + 1 < nt) {
            load_kv(sb, (t + 1) & 1, tid, b, (t + 1) * 64, h, Kh, Kl, Vh, Vl);
            CP_COMMIT();
            CP_WAIT(1);
        } else {
            CP_WAIT(0);
        }
        __syncthreads();

        const int k0 = t * 64;
        const int rowmax = q0 + wrow + 15;
        if (k0 <= rowmax) {       // warp-level causal skip
            const uint32_t kb  = sb + 2 * QBYTES + (t & 1) * KVSTG;
            const uint32_t klb = kb + 17408;
            const uint32_t vhb = kb + 34816;
            const uint32_t vlb = kb + 52224;

            float sf[8][4];
#pragma unroll
            for (int i = 0; i < 8; i++)
#pragma unroll
                for (int j = 0; j < 4; j++) sf[i][j] = 0.f;

#pragma unroll
            for (int kc = 0; kc < 8; kc++) {
#pragma unroll
                for (int g = 0; g < 4; g++) {
                    const uint32_t off = (g * 16 + lr) * APITCH + (kc * 2 + lh) * 16;
                    uint32_t bhf[4], blf[4];
                    ldsm4(bhf, kb + off);
                    ldsm4(blf, klb + off);
#pragma unroll
                    for (int n2 = 0; n2 < 2; n2++) {
                        float* cc = sf[g * 2 + n2];
                        mma16816(cc, qfh[kc], bhf[n2], bhf[n2 + 2]);
                        mma16816(cc, qfh[kc], blf[n2], blf[n2 + 2]);
                        mma16816(cc, qfl[kc], bhf[n2], bhf[n2 + 2]);
                    }
                }
            }

            if (k0 + 63 > q0 + wrow) {
#pragma unroll
                for (int g8 = 0; g8 < 8; g8++)
#pragma unroll
                    for (int c = 0; c < 4; c++) {
                        const int key = k0 + g8 * 8 + tig * 2 + (c & 1);
                        const int row = q0 + wrow + gid + ((c >> 1) * 8);
                        if (key > row) sf[g8][c] = -1e30f;
                    }
            }

#pragma unroll
            for (int r = 0; r < 2; r++) {
                float tm = -1e30f;
#pragma unroll
                for (int g8 = 0; g8 < 8; g8++)
                    tm = fmaxf(tm, fmaxf(sf[g8][r * 2], sf[g8][r * 2 + 1]));
                tm = fmaxf(tm, __shfl_xor_sync(0xffffffffu, tm, 1));
                tm = fmaxf(tm, __shfl_xor_sync(0xffffffffu, tm, 2));
                const float nm = fmaxf(m_[r], tm);
                const float fac = __expf(m_[r] - nm);
                m_[r] = nm;
                float rs = 0.f;
#pragma unroll
                for (int g8 = 0; g8 < 8; g8++) {
                    const float p0 = __expf(sf[g8][r * 2] - nm);
                    const float p1 = __expf(sf[g8][r * 2 + 1] - nm);
                    sf[g8][r * 2] = p0; sf[g8][r * 2 + 1] = p1;
                    rs += p0 + p1;
                }
                rs += __shfl_xor_sync(0xffffffffu, rs, 1);
                rs += __shfl_xor_sync(0xffffffffu, rs, 2);
                l_[r] = l_[r] * fac + rs;
#pragma unroll
                for (int n16 = 0; n16 < 16; n16++) {
                    oacc[n16][r * 2] *= fac;
                    oacc[n16][r * 2 + 1] *= fac;
                }
            }

#pragma unroll
            for (int kc2 = 0; kc2 < 4; kc2++) {
                uint32_t ph[4], pl[4];
#pragma unroll
                for (int q = 0; q < 4; q++) {
                    const float a = sf[2 * kc2 + (q >> 1)][(q & 1) * 2];
                    const float bfv = sf[2 * kc2 + (q >> 1)][(q & 1) * 2 + 1];
                    __nv_bfloat162 hb, lb;
                    split2(a, bfv, hb, lb);
                    ph[q] = *(uint32_t*)&hb;
                    pl[q] = *(uint32_t*)&lb;
                }
#pragma unroll
                for (int vt = 0; vt < 8; vt++) {
                    const uint32_t off = (kc2 * 16 + lr) * APITCH + (vt * 16 + lh * 8) * 2;
                    uint32_t vhf[4], vlf[4];
                    ldsm4t(vhf, vhb + off);
                    ldsm4t(vlf, vlb + off);
                    float* c0 = oacc[vt * 2];
                    float* c1 = oacc[vt * 2 + 1];
                    mma16816(c0, ph, vhf[0], vhf[1]);
                    mma16816(c1, ph, vhf[2], vhf[3]);
                    mma16816(c0, pl, vhf[0], vhf[1]);
                    mma16816(c1, pl, vhf[2], vhf[3]);
                    mma16816(c0, ph, vlf[0], vlf[1]);
                    mma16816(c1, ph, vlf[2], vlf[3]);
                }
            }
        }
        __syncthreads();
    }

    const float inv0 = 1.f / l_[0];
    const float inv1 = 1.f / l_[1];
#pragma unroll
    for (int n16 = 0; n16 < 16; n16++) {
#pragma unroll
        for (int r = 0; r < 2; r++) {
            const float inv = r ? inv1 : inv0;
            const int row = q0 + wrow + gid + r * 8;
            const int col = n16 * 8 + tig * 2;
            const float f0 = oacc[n16][r * 2] * inv;
            const float f1 = oacc[n16][r * 2 + 1] * inv;
            __nv_bfloat162 hb, lb;
            split2(f0, f1, hb, lb);
            const size_t g = (size_t)(b * LL + row) * DD + h * DHd + col;
            *(__nv_bfloat162*)(Oh + g) = hb;
            *(__nv_bfloat162*)(Ol + g) = lb;
        }
    }
}

// ---------------------------------------------------------------------------
extern "C" void kernel_launch(void* const* d_in, const int* in_sizes, int n_in,
                              void* d_out, int out_size)
{
    const float* x    = (const float*)d_in[0];
    const float* cosb = (const float*)d_in[2];
    const float* sinb = (const float*)d_in[3];
    const float* wq   = (const float*)d_in[4];
    const float* wk   = (const float*)d_in[5];
    const float* wv   = (const float*)d_in[6];
    const float* wo   = (const float*)d_in[7];
    float* out = (float*)d_out;

    __nv_bfloat16 *ah, *al, *wh, *wl, *qh, *ql, *kh, *kl, *vh, *vl, *oh, *ol;
    cudaGetSymbolAddress((void**)&ah, g_ah);
    cudaGetSymbolAddress((void**)&al, g_al);
    cudaGetSymbolAddress((void**)&wh, g_wh);
    cudaGetSymbolAddress((void**)&wl, g_wl);
    cudaGetSymbolAddress((void**)&qh, g_qh);
    cudaGetSymbolAddress((void**)&ql, g_ql);
    cudaGetSymbolAddress((void**)&kh, g_kh);
    cudaGetSymbolAddress((void**)&kl, g_kl);
    cudaGetSymbolAddress((void**)&vh, g_vh);
    cudaGetSymbolAddress((void**)&vl, g_vl);
    cudaGetSymbolAddress((void**)&oh, g_oh);
    cudaGetSymbolAddress((void**)&ol, g_ol);

    const int n4x = MM * DD / 4;
    const int n4w = SLW / 4;

    split_bf16<<<n4x / 256, 256>>>(x, ah, al);
    split_w4<<<dim3(n4w / 256, 4), 256>>>(wq, wk, wv, wo, wh, wl);

    cudaFuncSetAttribute(gemm64, cudaFuncAttributeMaxDynamicSharedMemorySize, GSMEM);
    cudaFuncSetAttribute(attn_mma, cudaFuncAttributeMaxDynamicSharedMemorySize, ASMEM);

    // QKV: one merged launch (z = 0,1,2)
    dim3 gqkv(DD / 64, MM / 128, 3);   // 32 x 32 x 3 = 3072 CTAs
    gemm64<<<gqkv, 256, GSMEM>>>(ah, al, wh, wl, nullptr,
                                 qh, ql, kh, kl, vh, vl, cosb, sinb, 1);

    attn_mma<<<dim3(LL / 128, Bb * HH), 256, ASMEM>>>(qh, ql, kh, kl, vh, vl, oh, ol);

    // O projection (fp32 out)
    dim3 go(DD / 64, MM / 128, 1);     // 1024 CTAs
    gemm64<<<go, 256, GSMEM>>>(oh, ol, wh + 3 * (size_t)SLW, wl + 3 * (size_t)SLW,
                               out, nullptr, nullptr, nullptr, nullptr, nullptr, nullptr,
                               cosb, sinb, 0);
}